// round 2
// baseline (speedup 1.0000x reference)
#include <cuda_runtime.h>
#include <math.h>

// ---------------- scratch (device globals; no allocation) ----------------
__device__ float g_lat [256*256];          // latent (B, 256)
__device__ float g_latT[256*256];          // latent transposed (256, B)
__device__ float g_x1 [2][256*128*16];     // conv1 output, h/w branches (B,128,16)
__device__ float g_y2 [2][256*256*31];     // conv2 raw output (B,256,31)
__device__ float g_ab [2][512];            // per-channel BN affine: a[co], b[256+co]
__device__ float g_c  [256*512*3];         // c branch (B,512,3), post BN+lrelu
__device__ float g_hw [2][256*512*32];     // h/w final (B,512,32), post tanh

// ---------------- kernel 1: latent = [lrelu(bn(noise@W^T)), emb[label]] ----------------
__global__ __launch_bounds__(256) void k_latent(
    const float* __restrict__ noise, const int* __restrict__ label,
    const float* __restrict__ lin_w, const float* __restrict__ bn0_g,
    const float* __restrict__ bn0_b, const float* __restrict__ emb)
{
    const int ch = blockIdx.x;   // 0..255
    const int b  = threadIdx.x;  // 0..255
    if (ch >= 128) {
        const int c2 = ch - 128;
        float v = emb[label[b]*128 + c2];
        g_lat [b*256 + ch] = v;
        g_latT[ch*256 + b] = v;
        return;
    }
    __shared__ float wsm[100];
    if (b < 100) wsm[b] = lin_w[ch*100 + b];
    __syncthreads();
    const float* nr = noise + b*100;
    float z = 0.f;
    #pragma unroll 4
    for (int i = 0; i < 100; i++) z += nr[i]*wsm[i];
    // lin_b omitted: constant per channel, cancels in BN mean subtraction.
    __shared__ float s1[256], s2[256];
    s1[b] = z; s2[b] = z*z; __syncthreads();
    for (int off = 128; off > 0; off >>= 1) {
        if (b < off) { s1[b] += s1[b+off]; s2[b] += s2[b+off]; }
        __syncthreads();
    }
    float m    = s1[0] * (1.f/256.f);
    float var  = s2[0] * (1.f/256.f) - m*m;
    float a    = bn0_g[ch] * rsqrtf(var + 1e-5f);
    float y    = (z - m)*a + bn0_b[ch];
    y = (y >= 0.f) ? y : 0.01f*y;
    g_lat [b*256 + ch] = y;
    g_latT[ch*256 + b] = y;
}

// ---------------- kernel 2: conv1 (length-1 convT == GEMM) + fused BN + lrelu ----------------
// MODE 0 -> write g_c ; MODE 1 -> write g_x1[br]
template<int L, int COPB, int COUT, int MODE>
__global__ __launch_bounds__(256) void k_conv1(
    const float* __restrict__ W, const float* __restrict__ gamma,
    const float* __restrict__ beta, float slope, int br)
{
    const int b   = threadIdx.x;
    const int co0 = blockIdx.x * COPB;
    __shared__ float wsm[COPB*256*L];
    for (int idx = b; idx < COPB*256*L; idx += 256) {
        int j   = idx / (256*L);
        int rem = idx - j*(256*L);
        int ci  = rem / L;
        int l   = rem - ci*L;
        wsm[idx] = W[(ci*COUT + co0 + j)*L + l];  // torch layout (Cin,Cout,K)
    }
    __syncthreads();
    float acc[COPB][L];
    #pragma unroll
    for (int j = 0; j < COPB; j++)
        #pragma unroll
        for (int l = 0; l < L; l++) acc[j][l] = 0.f;
    for (int ci = 0; ci < 256; ci++) {
        float xv = g_latT[ci*256 + b];
        #pragma unroll
        for (int j = 0; j < COPB; j++)
            #pragma unroll
            for (int l = 0; l < L; l++)
                acc[j][l] += xv * wsm[(j*256 + ci)*L + l];
    }
    __shared__ float s1[256], s2[256];
    #pragma unroll
    for (int j = 0; j < COPB; j++) {
        const int co = co0 + j;
        float s = 0.f, q = 0.f;
        #pragma unroll
        for (int l = 0; l < L; l++) { s += acc[j][l]; q += acc[j][l]*acc[j][l]; }
        s1[b] = s; s2[b] = q; __syncthreads();
        for (int off = 128; off > 0; off >>= 1) {
            if (b < off) { s1[b] += s1[b+off]; s2[b] += s2[b+off]; }
            __syncthreads();
        }
        const float inv = 1.f/(256.f*(float)L);
        float m   = s1[0]*inv;
        float var = s2[0]*inv - m*m;
        float a   = gamma[co]*rsqrtf(var + 1e-5f);
        float bs  = beta[co] - m*a;
        float* outp = (MODE == 0) ? (g_c + (b*COUT + co)*L)
                                  : (g_x1[br] + (b*COUT + co)*L);
        #pragma unroll
        for (int l = 0; l < L; l++) {
            float y = acc[j][l]*a + bs;
            outp[l] = (y >= 0.f) ? y : slope*y;
        }
        __syncthreads();
    }
}

// ---------------- kernel 3: conv2 (B,128,16)->(B,256,31), raw output ----------------
__global__ __launch_bounds__(256) void k_conv2(const float* __restrict__ W2, int br)
{
    const int tid = threadIdx.x;
    const int tb  = tid & 15, tco = tid >> 4;
    const int co0 = blockIdx.x*16, b0 = blockIdx.y*16;
    const float* __restrict__ x1 = g_x1[br];
    __shared__ float xs[16*16*17];  // [(ci*16+l)*17 + b]
    __shared__ float ws[16*16*17];  // [(ci*16+k)*17 + co]
    float acc[31];
    #pragma unroll
    for (int t = 0; t < 31; t++) acc[t] = 0.f;
    for (int cc = 0; cc < 8; cc++) {
        const int ci0 = cc*16;
        __syncthreads();
        for (int idx = tid; idx < 4096; idx += 256) {
            int bb = idx >> 8, rem = idx & 255;
            int ci = rem >> 4, l = rem & 15;
            xs[(ci*16 + l)*17 + bb] = x1[(b0+bb)*2048 + (ci0+ci)*16 + l];
        }
        for (int idx = tid; idx < 4096; idx += 256) {
            int ci = idx >> 8, rem = idx & 255;
            int co = rem >> 4, k = rem & 15;
            ws[(ci*16 + k)*17 + co] = W2[((ci0+ci)*256 + co0+co)*16 + k];
        }
        __syncthreads();
        for (int ci = 0; ci < 16; ci++) {
            float xv[16], wv[16];
            #pragma unroll
            for (int l = 0; l < 16; l++) xv[l] = xs[(ci*16 + l)*17 + tb];
            #pragma unroll
            for (int k = 0; k < 16; k++) wv[k] = ws[(ci*16 + k)*17 + tco];
            #pragma unroll
            for (int l = 0; l < 16; l++)
                #pragma unroll
                for (int k = 0; k < 16; k++)
                    acc[l+k] += xv[l]*wv[k];
        }
    }
    float* o = g_y2[br] + ((b0+tb)*256 + co0+tco)*31;
    #pragma unroll
    for (int t = 0; t < 31; t++) o[t] = acc[t];  // bias omitted: cancels in BN
}

// ---------------- kernel 4: per-channel BN stats over (b,t) for conv2 output ----------------
__global__ __launch_bounds__(256) void k_bnstats(
    const float* __restrict__ gamma, const float* __restrict__ beta, int br)
{
    const int co = blockIdx.x;
    const int b  = threadIdx.x;
    const float* p = g_y2[br] + (b*256 + co)*31;
    float s = 0.f, q = 0.f;
    #pragma unroll
    for (int t = 0; t < 31; t++) { float v = p[t]; s += v; q += v*v; }
    __shared__ float s1[256], s2[256];
    s1[b] = s; s2[b] = q; __syncthreads();
    for (int off = 128; off > 0; off >>= 1) {
        if (b < off) { s1[b] += s1[b+off]; s2[b] += s2[b+off]; }
        __syncthreads();
    }
    if (b == 0) {
        const float inv = 1.f/(256.f*31.f);
        float m   = s1[0]*inv;
        float var = s2[0]*inv - m*m;
        float a   = gamma[co]*rsqrtf(var + 1e-5f);
        g_ab[br][co]       = a;
        g_ab[br][256 + co] = beta[co] - m*a;
    }
}

// ---------------- kernel 5: conv3 (B,256,31)->(B,512,32), BN+lrelu on load, tanh on store ----
__global__ __launch_bounds__(256) void k_conv3(
    const float* __restrict__ W3, const float* __restrict__ bias, int br)
{
    const int tid = threadIdx.x;
    const int tb  = tid & 15, tc = tid >> 4;      // tc handles couts tc and tc+16
    const int co0 = blockIdx.x*32, b0 = blockIdx.y*16;
    const float* __restrict__ y2 = g_y2[br];
    const float* __restrict__ ab = g_ab[br];
    __shared__ float xs[496*17];   // [(ci*31+t)*17 + b], 16 ci per chunk
    __shared__ float ws[1024];     // [ci*64 + co*2 + k]
    float acc[2][32];
    const float bi0 = bias[co0 + tc], bi1 = bias[co0 + tc + 16];
    #pragma unroll
    for (int t = 0; t < 32; t++) { acc[0][t] = bi0; acc[1][t] = bi1; }
    for (int cc = 0; cc < 16; cc++) {
        const int ci0 = cc*16;
        __syncthreads();
        for (int idx = tid; idx < 7936; idx += 256) {
            int bb  = idx / 496;
            int rem = idx - bb*496;
            int ci  = rem / 31;
            int t   = rem - ci*31;
            float v  = y2[((b0+bb)*256 + ci0+ci)*31 + t];
            float a  = ab[ci0+ci], b2 = ab[256 + ci0+ci];
            v = a*v + b2;
            v = (v >= 0.f) ? v : 0.2f*v;
            xs[(ci*31 + t)*17 + bb] = v;
        }
        for (int idx = tid; idx < 1024; idx += 256) {
            int ci  = idx >> 6;
            int rem = idx & 63;  // co*2 + k
            ws[idx] = W3[((ci0+ci)*512 + co0)*2 + rem];
        }
        __syncthreads();
        for (int ci = 0; ci < 16; ci++) {
            float w00 = ws[ci*64 + tc*2],        w01 = ws[ci*64 + tc*2 + 1];
            float w10 = ws[ci*64 + (tc+16)*2],   w11 = ws[ci*64 + (tc+16)*2 + 1];
            #pragma unroll
            for (int t = 0; t < 31; t++) {
                float xc = xs[(ci*31 + t)*17 + tb];
                acc[0][t]   += xc*w00;
                acc[0][t+1] += xc*w01;
                acc[1][t]   += xc*w10;
                acc[1][t+1] += xc*w11;
            }
        }
    }
    #pragma unroll
    for (int j = 0; j < 2; j++) {
        float* o = g_hw[br] + ((b0+tb)*512 + co0 + tc + j*16)*32;
        #pragma unroll
        for (int t = 0; t < 32; t++) o[t] = tanhf(acc[j][t]);
    }
}

// ---------------- kernel 6: out[b,ch,hh,ww] = sum_r coef[r]*c[b,r,ch]*h[b,r,hh]*w[b,r,ww] ----
__global__ __launch_bounds__(256) void k_final(const float* __restrict__ coef,
                                               float* __restrict__ out)
{
    const int b   = blockIdx.x;
    const int tid = threadIdx.x;
    __shared__ __align__(16) float4 cs[128];
    __shared__ __align__(16) float  hs [128*32];
    __shared__ __align__(16) float  ws2[128*32];
    const int p0  = tid*4;
    const int hh  = p0 >> 5;
    const int ww0 = p0 & 31;
    float acc[4][3];
    #pragma unroll
    for (int i = 0; i < 4; i++)
        #pragma unroll
        for (int c = 0; c < 3; c++) acc[i][c] = 0.f;
    for (int chk = 0; chk < 4; chk++) {
        const int r0 = chk*128;
        __syncthreads();
        if (tid < 128) {
            const float* cp = g_c + (b*512 + r0 + tid)*3;
            float cf = coef[r0 + tid];
            cs[tid] = make_float4(cp[0]*cf, cp[1]*cf, cp[2]*cf, 0.f);
        }
        for (int idx = tid; idx < 4096; idx += 256) {
            hs [idx] = g_hw[0][(b*512 + r0)*32 + idx];
            ws2[idx] = g_hw[1][(b*512 + r0)*32 + idx];
        }
        __syncthreads();
        for (int r = 0; r < 128; r++) {
            float4 c4 = cs[r];
            float  hv = hs[r*32 + hh];
            float4 wv = *reinterpret_cast<const float4*>(&ws2[r*32 + ww0]);
            float p;
            p = hv*wv.x; acc[0][0] += p*c4.x; acc[0][1] += p*c4.y; acc[0][2] += p*c4.z;
            p = hv*wv.y; acc[1][0] += p*c4.x; acc[1][1] += p*c4.y; acc[1][2] += p*c4.z;
            p = hv*wv.z; acc[2][0] += p*c4.x; acc[2][1] += p*c4.y; acc[2][2] += p*c4.z;
            p = hv*wv.w; acc[3][0] += p*c4.x; acc[3][1] += p*c4.y; acc[3][2] += p*c4.z;
        }
    }
    #pragma unroll
    for (int c = 0; c < 3; c++)
        #pragma unroll
        for (int i = 0; i < 4; i++)
            out[((b*3 + c)*32 + hh)*32 + ww0 + i] = acc[i][c];
}

// ---------------- launch ----------------
extern "C" void kernel_launch(void* const* d_in, const int* in_sizes, int n_in,
                              void* d_out, int out_size)
{
    const float* noise = (const float*)d_in[0];
    const int*   label = (const int*)  d_in[1];
    const float* lin_w = (const float*)d_in[2];
    // d_in[3] lin_b: cancels in BN
    const float* bn0_g = (const float*)d_in[4];
    const float* bn0_b = (const float*)d_in[5];
    const float* emb   = (const float*)d_in[6];
    const float* c_w1  = (const float*)d_in[7];
    const float* c_g1  = (const float*)d_in[9];
    const float* c_be1 = (const float*)d_in[10];
    const float* h_w1  = (const float*)d_in[11];
    const float* h_g1  = (const float*)d_in[13];
    const float* h_be1 = (const float*)d_in[14];
    const float* h_w2  = (const float*)d_in[15];
    const float* h_g2  = (const float*)d_in[17];
    const float* h_be2 = (const float*)d_in[18];
    const float* h_w3  = (const float*)d_in[19];
    const float* h_b3  = (const float*)d_in[20];
    const float* w_w1  = (const float*)d_in[21];
    const float* w_g1  = (const float*)d_in[23];
    const float* w_be1 = (const float*)d_in[24];
    const float* w_w2  = (const float*)d_in[25];
    const float* w_g2  = (const float*)d_in[27];
    const float* w_be2 = (const float*)d_in[28];
    const float* w_w3  = (const float*)d_in[29];
    const float* w_b3  = (const float*)d_in[30];
    const float* coef  = (const float*)d_in[31];
    float* out = (float*)d_out;

    k_latent<<<256, 256>>>(noise, label, lin_w, bn0_g, bn0_b, emb);

    k_conv1<3, 8, 512, 0><<<64, 256>>>(c_w1, c_g1, c_be1, 0.2f, 0);
    k_conv1<16, 2, 128, 1><<<64, 256>>>(h_w1, h_g1, h_be1, 0.2f, 0);
    k_conv1<16, 2, 128, 1><<<64, 256>>>(w_w1, w_g1, w_be1, 0.2f, 1);

    k_conv2<<<dim3(16, 16), 256>>>(h_w2, 0);
    k_conv2<<<dim3(16, 16), 256>>>(w_w2, 1);

    k_bnstats<<<256, 256>>>(h_g2, h_be2, 0);
    k_bnstats<<<256, 256>>>(w_g2, w_be2, 1);

    k_conv3<<<dim3(16, 16), 256>>>(h_w3, h_b3, 0);
    k_conv3<<<dim3(16, 16), 256>>>(w_w3, w_b3, 1);

    k_final<<<256, 256>>>(coef, out);
}

// round 3
// speedup vs baseline: 1.1218x; 1.1218x over previous
#include <cuda_runtime.h>
#include <math.h>

typedef unsigned long long u64;

// ---------------- f32x2 helpers ----------------
__device__ __forceinline__ u64 d_pack(float lo, float hi) {
    u64 r; asm("mov.b64 %0, {%1,%2};" : "=l"(r) : "f"(lo), "f"(hi)); return r;
}
__device__ __forceinline__ u64 d_dup(float x) { return d_pack(x, x); }
__device__ __forceinline__ void d_unpack(u64 v, float& lo, float& hi) {
    asm("mov.b64 {%0,%1}, %2;" : "=f"(lo), "=f"(hi) : "l"(v));
}
__device__ __forceinline__ u64 d_fma2(u64 a, u64 b, u64 c) {
    u64 d; asm("fma.rn.f32x2 %0, %1, %2, %3;" : "=l"(d) : "l"(a), "l"(b), "l"(c)); return d;
}

// ---------------- scratch (device globals; no allocation) ----------------
__device__ float g_latT [256*256];          // latent transposed (256 ci, 256 b)
__device__ float g_craw [256*1536];         // c conv1 raw (B, 512*3)
__device__ float g_x1raw[2][256*2048];      // h/w conv1 raw (B, 128*16)
__device__ float g_y2   [2][256*256*31];    // conv2 raw output (B,256,31)
__device__ float g_abc  [2][512];           // BN affine c branch: [0]=a, [1]=shift
__device__ float g_abhw [2][2][128];        // BN affine conv1 h/w
__device__ float g_ab2  [2][2][256];        // BN affine conv2 h/w
__device__ float g_hw   [2][256*512*32];    // h/w final (B,512,32), post tanh

// ---------------- kernel 1: latent ----------------
__global__ __launch_bounds__(256) void k_latent(
    const float* __restrict__ noise, const int* __restrict__ label,
    const float* __restrict__ lin_w, const float* __restrict__ bn0_g,
    const float* __restrict__ bn0_b, const float* __restrict__ emb)
{
    const int ch = blockIdx.x, b = threadIdx.x;
    if (ch >= 128) {
        g_latT[ch*256 + b] = emb[label[b]*128 + (ch - 128)];
        return;
    }
    __shared__ float wsm[100];
    if (b < 100) wsm[b] = lin_w[ch*100 + b];
    __syncthreads();
    const float* nr = noise + b*100;
    float z = 0.f;
    #pragma unroll 4
    for (int i = 0; i < 100; i++) z += nr[i]*wsm[i];
    // lin_b cancels in BN mean subtraction.
    __shared__ float s1[256], s2[256];
    s1[b] = z; s2[b] = z*z; __syncthreads();
    for (int off = 128; off > 0; off >>= 1) {
        if (b < off) { s1[b] += s1[b+off]; s2[b] += s2[b+off]; }
        __syncthreads();
    }
    float m   = s1[0]*(1.f/256.f);
    float var = s2[0]*(1.f/256.f) - m*m;
    float a   = bn0_g[ch]*rsqrtf(var + 1e-5f);
    float y   = (z - m)*a + bn0_b[ch];
    g_latT[ch*256 + b] = (y >= 0.f) ? y : 0.01f*y;
}

// ---------------- kernel 2: conv1 as plain GEMM (raw, no BN yet) ----------------
// out[b,n] = sum_ci latT[ci,b] * W[ci*N + n]   (torch (Cin,Cout,K) is row-major (Cin, Cout*K))
// mode 0: c branch -> g_craw (N=1536). mode 1: z selects h/w -> g_x1raw[z] (N=2048).
__global__ __launch_bounds__(256) void k_gemm1(
    const float* __restrict__ W0, const float* __restrict__ W1, int N, int mode)
{
    const float* __restrict__ W = (mode == 0) ? W0 : (blockIdx.z ? W1 : W0);
    float* __restrict__ O = (mode == 0) ? g_craw : g_x1raw[blockIdx.z];
    const int n0 = blockIdx.x*64, b0 = blockIdx.y*64;
    const int tid = threadIdx.x, tx = tid & 15, ty = tid >> 4;
    __shared__ float Xs[16][68], Ws[16][68];
    float acc[4][4] = {};
    for (int k0 = 0; k0 < 256; k0 += 16) {
        __syncthreads();
        for (int i = tid; i < 1024; i += 256) {
            int k = i >> 6, c = i & 63;
            Xs[k][c] = g_latT[(k0+k)*256 + b0 + c];
            Ws[k][c] = W[(k0+k)*N + n0 + c];
        }
        __syncthreads();
        #pragma unroll
        for (int k = 0; k < 16; k++) {
            float4 x4 = *(const float4*)&Xs[k][ty*4];
            float4 w4 = *(const float4*)&Ws[k][tx*4];
            float xa[4] = {x4.x, x4.y, x4.z, x4.w};
            float wa[4] = {w4.x, w4.y, w4.z, w4.w};
            #pragma unroll
            for (int i = 0; i < 4; i++)
                #pragma unroll
                for (int j = 0; j < 4; j++) acc[i][j] += xa[i]*wa[j];
        }
    }
    #pragma unroll
    for (int i = 0; i < 4; i++) {
        float4 v = make_float4(acc[i][0], acc[i][1], acc[i][2], acc[i][3]);
        *(float4*)&O[(b0 + ty*4 + i)*N + n0 + tx*4] = v;
    }
}

// ---------------- kernel 3: BN stats for all conv1 channels ----------------
// blocks 0..511: c branch (L=3). blocks 512..767: h/w (L=16).
__global__ __launch_bounds__(256) void k_bnstats1(
    const float* __restrict__ cg, const float* __restrict__ cb,
    const float* __restrict__ hg, const float* __restrict__ hb,
    const float* __restrict__ wg, const float* __restrict__ wb)
{
    const int bid = blockIdx.x, b = threadIdx.x;
    float s = 0.f, q = 0.f; float invn; float gam, bet;
    int which, br = 0, co;
    if (bid < 512) {
        which = 0; co = bid;
        const float* p = g_craw + b*1536 + co*3;
        #pragma unroll
        for (int l = 0; l < 3; l++) { float v = p[l]; s += v; q += v*v; }
        invn = 1.f/(256.f*3.f); gam = cg[co]; bet = cb[co];
    } else {
        which = 1; int idx = bid - 512; br = idx >> 7; co = idx & 127;
        const float* p = g_x1raw[br] + b*2048 + co*16;
        #pragma unroll
        for (int l = 0; l < 16; l++) { float v = p[l]; s += v; q += v*v; }
        invn = 1.f/(256.f*16.f);
        gam = br ? wg[co] : hg[co]; bet = br ? wb[co] : hb[co];
    }
    __shared__ float s1[256], s2[256];
    s1[b] = s; s2[b] = q; __syncthreads();
    for (int off = 128; off > 0; off >>= 1) {
        if (b < off) { s1[b] += s1[b+off]; s2[b] += s2[b+off]; }
        __syncthreads();
    }
    if (b == 0) {
        float m   = s1[0]*invn;
        float var = s2[0]*invn - m*m;
        float a   = gam*rsqrtf(var + 1e-5f);
        float sh  = bet - m*a;
        if (which == 0) { g_abc[0][co] = a; g_abc[1][co] = sh; }
        else            { g_abhw[br][0][co] = a; g_abhw[br][1][co] = sh; }
    }
}

// ---------------- kernel 4: conv2 (B,128,16)->(B,256,31) with f32x2 FMAs ----------------
// BN+lrelu(0.2) of conv1 applied on smem load. Raw output (its BN comes later).
__global__ __launch_bounds__(256) void k_conv2(
    const float* __restrict__ W2h, const float* __restrict__ W2w)
{
    const int br = blockIdx.z;
    const float* __restrict__ W2 = br ? W2w : W2h;
    const float* __restrict__ x1 = g_x1raw[br];
    const float* __restrict__ aA = g_abhw[br][0];
    const float* __restrict__ aS = g_abhw[br][1];
    const int tid = threadIdx.x, tb = tid & 15, tco = tid >> 4;
    const int co0 = blockIdx.x*16, b0 = blockIdx.y*16;
    __shared__ float xs[16*16*17];   // [(ci*16+l)*17 + b]
    __shared__ u64  ws2[16*8*17];    // [(ci*8+j)*17 + co], lanes (k=2j, 2j+1)
    u64 A[15], B[15];
    #pragma unroll
    for (int p = 0; p < 15; p++) { A[p] = 0ull; B[p] = 0ull; }
    for (int cc = 0; cc < 8; cc++) {
        const int ci0 = cc*16;
        __syncthreads();
        for (int idx = tid; idx < 4096; idx += 256) {
            int bb = idx >> 8, ci = (idx >> 4) & 15, l = idx & 15;
            float raw = x1[(b0+bb)*2048 + (ci0+ci)*16 + l];
            float v = fmaf(aA[ci0+ci], raw, aS[ci0+ci]);
            v = (v >= 0.f) ? v : 0.2f*v;
            xs[(ci*16 + l)*17 + bb] = v;
        }
        for (int idx = tid; idx < 2048; idx += 256) {
            int ci = idx >> 7, co = (idx >> 3) & 15, j = idx & 7;
            float2 wv = *(const float2*)&W2[((ci0+ci)*256 + co0+co)*16 + 2*j];
            ws2[(ci*8 + j)*17 + co] = d_pack(wv.x, wv.y);
        }
        __syncthreads();
        #pragma unroll
        for (int ci = 0; ci < 16; ci++) {
            u64 w2r[8];
            #pragma unroll
            for (int j = 0; j < 8; j++) w2r[j] = ws2[(ci*8 + j)*17 + tco];
            #pragma unroll
            for (int l2 = 0; l2 < 8; l2++) {
                u64 xe = d_dup(xs[(ci*16 + 2*l2)*17 + tb]);
                #pragma unroll
                for (int j = 0; j < 8; j++) A[l2+j] = d_fma2(xe, w2r[j], A[l2+j]);
                u64 xo = d_dup(xs[(ci*16 + 2*l2 + 1)*17 + tb]);
                #pragma unroll
                for (int j = 0; j < 8; j++) B[l2+j] = d_fma2(xo, w2r[j], B[l2+j]);
            }
        }
    }
    float y[31];
    #pragma unroll
    for (int p = 0; p < 15; p++) d_unpack(A[p], y[2*p], y[2*p+1]);
    y[30] = 0.f;
    #pragma unroll
    for (int p = 0; p < 15; p++) {
        float lo, hi; d_unpack(B[p], lo, hi);
        y[2*p+1] += lo; y[2*p+2] += hi;
    }
    float* o = g_y2[br] + ((b0+tb)*256 + co0+tco)*31;
    #pragma unroll
    for (int t = 0; t < 31; t++) o[t] = y[t];   // conv bias cancels in BN
}

// ---------------- kernel 5: BN stats for conv2 output ----------------
__global__ __launch_bounds__(256) void k_bnstats2(
    const float* __restrict__ hg, const float* __restrict__ hb,
    const float* __restrict__ wg, const float* __restrict__ wb)
{
    const int co = blockIdx.x, br = blockIdx.y, b = threadIdx.x;
    const float* p = g_y2[br] + (b*256 + co)*31;
    float s = 0.f, q = 0.f;
    #pragma unroll
    for (int t = 0; t < 31; t++) { float v = p[t]; s += v; q += v*v; }
    __shared__ float s1[256], s2[256];
    s1[b] = s; s2[b] = q; __syncthreads();
    for (int off = 128; off > 0; off >>= 1) {
        if (b < off) { s1[b] += s1[b+off]; s2[b] += s2[b+off]; }
        __syncthreads();
    }
    if (b == 0) {
        const float inv = 1.f/(256.f*31.f);
        float m   = s1[0]*inv;
        float var = s2[0]*inv - m*m;
        float gam = br ? wg[co] : hg[co];
        float bet = br ? wb[co] : hb[co];
        float a   = gam*rsqrtf(var + 1e-5f);
        g_ab2[br][0][co] = a;
        g_ab2[br][1][co] = bet - m*a;
    }
}

// ---------------- kernel 6: conv3 (B,256,31)->(B,512,32), f32x2, tanh epilogue ----------
__global__ __launch_bounds__(256) void k_conv3(
    const float* __restrict__ W3h, const float* __restrict__ W3w,
    const float* __restrict__ bh,  const float* __restrict__ bw)
{
    const int br = blockIdx.z;
    const float* __restrict__ W3   = br ? W3w : W3h;
    const float* __restrict__ bias = br ? bw  : bh;
    const float* __restrict__ y2 = g_y2[br];
    const float* __restrict__ aA = g_ab2[br][0];
    const float* __restrict__ aS = g_ab2[br][1];
    const int tid = threadIdx.x, tb = tid & 15, tc = tid >> 4;
    const int co0 = blockIdx.x*16, b0 = blockIdx.y*16;
    __shared__ u64  xs2[16*16*17];  // [(ci*16+j)*17 + b], lanes (t=2j, 2j+1), t=31 padded 0
    __shared__ float ws[512];       // [ci*32 + co*2 + k]
    u64 A[16], B[16];
    const float bi = bias[co0 + tc];
    #pragma unroll
    for (int j = 0; j < 16; j++) { A[j] = d_dup(bi); B[j] = 0ull; }
    for (int cc = 0; cc < 16; cc++) {
        const int ci0 = cc*16;
        __syncthreads();
        for (int idx = tid; idx < 4096; idx += 256) {
            int ci = idx >> 8, bb = (idx >> 4) & 15, j = idx & 15;
            const float* base = y2 + ((b0+bb)*256 + ci0+ci)*31;
            float a = aA[ci0+ci], sh = aS[ci0+ci];
            float v0 = fmaf(a, base[2*j], sh);
            v0 = (v0 >= 0.f) ? v0 : 0.2f*v0;
            float v1 = 0.f;
            if (j < 15) {
                v1 = fmaf(a, base[2*j+1], sh);
                v1 = (v1 >= 0.f) ? v1 : 0.2f*v1;
            }
            xs2[(ci*16 + j)*17 + bb] = d_pack(v0, v1);
        }
        for (int idx = tid; idx < 512; idx += 256)
            ws[idx] = W3[(ci0 + (idx >> 5))*1024 + co0*2 + (idx & 31)];
        __syncthreads();
        #pragma unroll
        for (int ci = 0; ci < 16; ci++) {
            u64 w0d = d_dup(ws[ci*32 + tc*2]);
            u64 w1d = d_dup(ws[ci*32 + tc*2 + 1]);
            #pragma unroll
            for (int j = 0; j < 16; j++) {
                u64 x2 = xs2[(ci*16 + j)*17 + tb];
                A[j] = d_fma2(x2, w0d, A[j]);
                B[j] = d_fma2(x2, w1d, B[j]);
            }
        }
    }
    float y[32];
    #pragma unroll
    for (int j = 0; j < 16; j++) d_unpack(A[j], y[2*j], y[2*j+1]);
    #pragma unroll
    for (int j = 0; j < 16; j++) {
        float lo, hi; d_unpack(B[j], lo, hi);
        y[2*j+1] += lo;
        if (j < 15) y[2*j+2] += hi;
    }
    float* o = g_hw[br] + ((b0+tb)*512 + co0+tc)*32;
    #pragma unroll
    for (int t = 0; t < 32; t++) o[t] = tanhf(y[t]);
}

// ---------------- kernel 7: out[b,ch,hh,ww] = sum_r coef[r]*c*h*w ----------------
__global__ __launch_bounds__(256) void k_final(const float* __restrict__ coef,
                                               float* __restrict__ out)
{
    const int b = blockIdx.x, tid = threadIdx.x;
    __shared__ __align__(16) float4 cs[128];
    __shared__ __align__(16) float  hs [128*32];
    __shared__ __align__(16) float  ws2[128*32];
    const int p0 = tid*4, hh = p0 >> 5, ww0 = p0 & 31;
    float acc[4][3];
    #pragma unroll
    for (int i = 0; i < 4; i++)
        #pragma unroll
        for (int c = 0; c < 3; c++) acc[i][c] = 0.f;
    for (int chk = 0; chk < 4; chk++) {
        const int r0 = chk*128;
        __syncthreads();
        if (tid < 128) {
            const int r = r0 + tid;
            const float* cp = g_craw + b*1536 + r*3;
            float a = g_abc[0][r], sh = g_abc[1][r];
            float cf = coef[r];
            float v0 = fmaf(a, cp[0], sh); v0 = (v0 >= 0.f) ? v0 : 0.2f*v0;
            float v1 = fmaf(a, cp[1], sh); v1 = (v1 >= 0.f) ? v1 : 0.2f*v1;
            float v2 = fmaf(a, cp[2], sh); v2 = (v2 >= 0.f) ? v2 : 0.2f*v2;
            cs[tid] = make_float4(v0*cf, v1*cf, v2*cf, 0.f);
        }
        for (int idx = tid; idx < 4096; idx += 256) {
            hs [idx] = g_hw[0][(b*512 + r0)*32 + idx];
            ws2[idx] = g_hw[1][(b*512 + r0)*32 + idx];
        }
        __syncthreads();
        for (int r = 0; r < 128; r++) {
            float4 c4 = cs[r];
            float  hv = hs[r*32 + hh];
            float4 wv = *reinterpret_cast<const float4*>(&ws2[r*32 + ww0]);
            float p;
            p = hv*wv.x; acc[0][0] += p*c4.x; acc[0][1] += p*c4.y; acc[0][2] += p*c4.z;
            p = hv*wv.y; acc[1][0] += p*c4.x; acc[1][1] += p*c4.y; acc[1][2] += p*c4.z;
            p = hv*wv.z; acc[2][0] += p*c4.x; acc[2][1] += p*c4.y; acc[2][2] += p*c4.z;
            p = hv*wv.w; acc[3][0] += p*c4.x; acc[3][1] += p*c4.y; acc[3][2] += p*c4.z;
        }
    }
    #pragma unroll
    for (int c = 0; c < 3; c++)
        #pragma unroll
        for (int i = 0; i < 4; i++)
            out[((b*3 + c)*32 + hh)*32 + ww0 + i] = acc[i][c];
}

// ---------------- launch ----------------
extern "C" void kernel_launch(void* const* d_in, const int* in_sizes, int n_in,
                              void* d_out, int out_size)
{
    const float* noise = (const float*)d_in[0];
    const int*   label = (const int*)  d_in[1];
    const float* lin_w = (const float*)d_in[2];
    const float* bn0_g = (const float*)d_in[4];
    const float* bn0_b = (const float*)d_in[5];
    const float* emb   = (const float*)d_in[6];
    const float* c_w1  = (const float*)d_in[7];
    const float* c_g1  = (const float*)d_in[9];
    const float* c_be1 = (const float*)d_in[10];
    const float* h_w1  = (const float*)d_in[11];
    const float* h_g1  = (const float*)d_in[13];
    const float* h_be1 = (const float*)d_in[14];
    const float* h_w2  = (const float*)d_in[15];
    const float* h_g2  = (const float*)d_in[17];
    const float* h_be2 = (const float*)d_in[18];
    const float* h_w3  = (const float*)d_in[19];
    const float* h_b3  = (const float*)d_in[20];
    const float* w_w1  = (const float*)d_in[21];
    const float* w_g1  = (const float*)d_in[23];
    const float* w_be1 = (const float*)d_in[24];
    const float* w_w2  = (const float*)d_in[25];
    const float* w_g2  = (const float*)d_in[27];
    const float* w_be2 = (const float*)d_in[28];
    const float* w_w3  = (const float*)d_in[29];
    const float* w_b3  = (const float*)d_in[30];
    const float* coef  = (const float*)d_in[31];
    float* out = (float*)d_out;

    k_latent<<<256, 256>>>(noise, label, lin_w, bn0_g, bn0_b, emb);

    k_gemm1<<<dim3(24, 4, 1), 256>>>(c_w1, c_w1, 1536, 0);
    k_gemm1<<<dim3(32, 4, 2), 256>>>(h_w1, w_w1, 2048, 1);

    k_bnstats1<<<768, 256>>>(c_g1, c_be1, h_g1, h_be1, w_g1, w_be1);

    k_conv2<<<dim3(16, 16, 2), 256>>>(h_w2, w_w2);

    k_bnstats2<<<dim3(256, 2), 256>>>(h_g2, h_be2, w_g2, w_be2);

    k_conv3<<<dim3(32, 16, 2), 256>>>(h_w3, w_w3, h_b3, w_b3);

    k_final<<<256, 256>>>(coef, out);
}

// round 7
// speedup vs baseline: 1.9028x; 1.6962x over previous
#include <cuda_runtime.h>
#include <cuda_bf16.h>
#include <math.h>
#include <stdint.h>

typedef uint32_t u32;

// ---------------- scratch (device globals; no allocation) ----------------
__device__ float g_latT [256*256];
__device__ float g_craw [256*1536];
__device__ float g_x1raw[2][256*2048];
__device__ float g_y2   [2][256*256*31];
__device__ float g_abc  [2][512];
__device__ float g_abhw [2][2][128];
__device__ float g_ab2  [2][2][256];
__device__ float g_hw   [2][256*512*32];
// bf16 hi/lo split operands for the mma GEMMs
__device__ __nv_bfloat16 g_A2h[2][4096*128], g_A2l[2][4096*128];
__device__ __nv_bfloat16 g_B2h[2][4096*128], g_B2l[2][4096*128];
__device__ __nv_bfloat16 g_A3h[2][8192*256], g_A3l[2][8192*256];
__device__ __nv_bfloat16 g_B3h[2][1024*256], g_B3l[2][1024*256];

__device__ __forceinline__ u32 packbf(float x, float y) {
    __nv_bfloat162 t;
    t.x = __float2bfloat16(x);
    t.y = __float2bfloat16(y);
    return *reinterpret_cast<u32*>(&t);
}
__device__ __forceinline__ void split_pair(float v0, float v1, u32& hw, u32& lw) {
    __nv_bfloat16 h0 = __float2bfloat16(v0), h1 = __float2bfloat16(v1);
    float r0 = v0 - __bfloat162float(h0), r1 = v1 - __bfloat162float(h1);
    __nv_bfloat162 th; th.x = h0; th.y = h1;
    hw = *reinterpret_cast<u32*>(&th);
    lw = packbf(r0, r1);
}

// mma.sync m16n8k16 bf16 (sm_80+, valid on sm_100 base)
#define MMA16816(c, a, b) \
    asm volatile("mma.sync.aligned.m16n8k16.row.col.f32.bf16.bf16.f32 " \
                 "{%0,%1,%2,%3}, {%4,%5,%6,%7}, {%8,%9}, {%0,%1,%2,%3};" \
                 : "+f"((c)[0]), "+f"((c)[1]), "+f"((c)[2]), "+f"((c)[3]) \
                 : "r"((a)[0]), "r"((a)[1]), "r"((a)[2]), "r"((a)[3]), \
                   "r"((b)[0]), "r"((b)[1]))

// ---------------- kernel 1: latent ----------------
__global__ __launch_bounds__(256) void k_latent(
    const float* __restrict__ noise, const int* __restrict__ label,
    const float* __restrict__ lin_w, const float* __restrict__ bn0_g,
    const float* __restrict__ bn0_b, const float* __restrict__ emb)
{
    const int ch = blockIdx.x, b = threadIdx.x;
    if (ch >= 128) {
        g_latT[ch*256 + b] = emb[label[b]*128 + (ch - 128)];
        return;
    }
    __shared__ float wsm[100];
    if (b < 100) wsm[b] = lin_w[ch*100 + b];
    __syncthreads();
    const float* nr = noise + b*100;
    float z = 0.f;
    #pragma unroll 4
    for (int i = 0; i < 100; i++) z += nr[i]*wsm[i];
    __shared__ float s1[256], s2[256];
    s1[b] = z; s2[b] = z*z; __syncthreads();
    for (int off = 128; off > 0; off >>= 1) {
        if (b < off) { s1[b] += s1[b+off]; s2[b] += s2[b+off]; }
        __syncthreads();
    }
    float m   = s1[0]*(1.f/256.f);
    float var = s2[0]*(1.f/256.f) - m*m;
    float a   = bn0_g[ch]*rsqrtf(var + 1e-5f);
    float y   = (z - m)*a + bn0_b[ch];
    g_latT[ch*256 + b] = (y >= 0.f) ? y : 0.01f*y;
}

// ---------------- kernel 2: conv1 GEMMs (raw) ----------------
__global__ __launch_bounds__(256) void k_gemm1(
    const float* __restrict__ W0, const float* __restrict__ W1, int N, int mode)
{
    const float* __restrict__ W = (mode == 0) ? W0 : (blockIdx.z ? W1 : W0);
    float* __restrict__ O = (mode == 0) ? g_craw : g_x1raw[blockIdx.z];
    const int n0 = blockIdx.x*64, b0 = blockIdx.y*64;
    const int tid = threadIdx.x, tx = tid & 15, ty = tid >> 4;
    __shared__ float Xs[16][68], Ws[16][68];
    float acc[4][4] = {};
    for (int k0 = 0; k0 < 256; k0 += 16) {
        __syncthreads();
        for (int i = tid; i < 1024; i += 256) {
            int k = i >> 6, c = i & 63;
            Xs[k][c] = g_latT[(k0+k)*256 + b0 + c];
            Ws[k][c] = W[(k0+k)*N + n0 + c];
        }
        __syncthreads();
        #pragma unroll
        for (int k = 0; k < 16; k++) {
            float4 x4 = *(const float4*)&Xs[k][ty*4];
            float4 w4 = *(const float4*)&Ws[k][tx*4];
            float xa[4] = {x4.x, x4.y, x4.z, x4.w};
            float wa[4] = {w4.x, w4.y, w4.z, w4.w};
            #pragma unroll
            for (int i = 0; i < 4; i++)
                #pragma unroll
                for (int j = 0; j < 4; j++) acc[i][j] += xa[i]*wa[j];
        }
    }
    #pragma unroll
    for (int i = 0; i < 4; i++) {
        float4 v = make_float4(acc[i][0], acc[i][1], acc[i][2], acc[i][3]);
        *(float4*)&O[(b0 + ty*4 + i)*N + n0 + tx*4] = v;
    }
}

// ---------------- kernel 3: BN stats conv1 ----------------
__global__ __launch_bounds__(256) void k_bnstats1(
    const float* __restrict__ cg, const float* __restrict__ cb,
    const float* __restrict__ hg, const float* __restrict__ hb,
    const float* __restrict__ wg, const float* __restrict__ wb)
{
    const int bid = blockIdx.x, b = threadIdx.x;
    float s = 0.f, q = 0.f; float invn; float gam, bet;
    int which, br = 0, co;
    if (bid < 512) {
        which = 0; co = bid;
        const float* p = g_craw + b*1536 + co*3;
        #pragma unroll
        for (int l = 0; l < 3; l++) { float v = p[l]; s += v; q += v*v; }
        invn = 1.f/(256.f*3.f); gam = cg[co]; bet = cb[co];
    } else {
        which = 1; int idx = bid - 512; br = idx >> 7; co = idx & 127;
        const float* p = g_x1raw[br] + b*2048 + co*16;
        #pragma unroll
        for (int l = 0; l < 16; l++) { float v = p[l]; s += v; q += v*v; }
        invn = 1.f/(256.f*16.f);
        gam = br ? wg[co] : hg[co]; bet = br ? wb[co] : hb[co];
    }
    __shared__ float s1[256], s2[256];
    s1[b] = s; s2[b] = q; __syncthreads();
    for (int off = 128; off > 0; off >>= 1) {
        if (b < off) { s1[b] += s1[b+off]; s2[b] += s2[b+off]; }
        __syncthreads();
    }
    if (b == 0) {
        float m   = s1[0]*invn;
        float var = s2[0]*invn - m*m;
        float a   = gam*rsqrtf(var + 1e-5f);
        float sh  = bet - m*a;
        if (which == 0) { g_abc[0][co] = a; g_abc[1][co] = sh; }
        else            { g_abhw[br][0][co] = a; g_abhw[br][1][co] = sh; }
    }
}

// ---------------- prep: split weights W2 -> B2 [br][n=co*16+k][ci], W3 -> B3 ----------------
__global__ __launch_bounds__(256) void k_prepB(
    const float* __restrict__ W2h, const float* __restrict__ W2w,
    const float* __restrict__ W3h, const float* __restrict__ W3w)
{
    int gid = blockIdx.x*256 + threadIdx.x;
    if (gid < 524288) {                       // W2: 2 br x 4096 n x 64 ci-pairs
        int br = gid >> 18, n = (gid >> 6) & 4095, cp = gid & 63;
        const float* W = br ? W2w : W2h;      // (ci,co,k) row-major = [ci][4096], n contiguous
        float v0 = W[(2*cp)*4096 + n];
        float v1 = W[(2*cp + 1)*4096 + n];
        u32 hw, lw; split_pair(v0, v1, hw, lw);
        ((u32*)g_B2h[br])[n*64 + cp] = hw;
        ((u32*)g_B2l[br])[n*64 + cp] = lw;
    } else {                                  // W3: 2 br x 1024 n x 128 ci-pairs
        int g2 = gid - 524288;
        int br = g2 >> 17, n = (g2 >> 7) & 1023, cp = g2 & 127;
        const float* W = br ? W3w : W3h;      // [ci][1024], n = co*2+k contiguous
        float v0 = W[(2*cp)*1024 + n];
        float v1 = W[(2*cp + 1)*1024 + n];
        u32 hw, lw; split_pair(v0, v1, hw, lw);
        ((u32*)g_B3h[br])[n*128 + cp] = hw;
        ((u32*)g_B3l[br])[n*128 + cp] = lw;
    }
}

// ---------------- prep: A2 = lrelu(bn(x1)) split, [br][m=b*16+l][ci] ----------------
__global__ __launch_bounds__(256) void k_prepA2()
{
    int gid = blockIdx.x*256 + threadIdx.x;   // 2 x 4096 x 64
    int br = gid >> 18, m = (gid >> 6) & 4095, cp = gid & 63;
    int b = m >> 4, l = m & 15;
    const float* x1 = g_x1raw[br];
    const float* aA = g_abhw[br][0];
    const float* aS = g_abhw[br][1];
    int ci = 2*cp;
    float v0 = fmaf(aA[ci],   x1[b*2048 + ci*16 + l],     aS[ci]);
    float v1 = fmaf(aA[ci+1], x1[b*2048 + (ci+1)*16 + l], aS[ci+1]);
    v0 = (v0 >= 0.f) ? v0 : 0.2f*v0;
    v1 = (v1 >= 0.f) ? v1 : 0.2f*v1;
    u32 hw, lw; split_pair(v0, v1, hw, lw);
    ((u32*)g_A2h[br])[m*64 + cp] = hw;
    ((u32*)g_A2l[br])[m*64 + cp] = lw;
}

// ---------------- kernel: conv2 via mma.sync (bf16 3-pass) ----------------
// C[(b,l)][(co,k)] = A2 @ B2^T over ci(128); fold y[b,co,t]=sum_{l+k=t} C.
extern __shared__ u32 smw[];
__global__ __launch_bounds__(256) void k_conv2m()
{
    const int br = blockIdx.z, nx = blockIdx.x, my = blockIdx.y;
    u32* AH = smw;          u32* AL = smw + 8704;
    u32* BH = smw + 17408;  u32* BL = smw + 26112;   // each 128 rows x 68 words
    const int tid = threadIdx.x, lane = tid & 31, wid = tid >> 5;
    const u32* gAH = (const u32*)g_A2h[br] + my*128*64;
    const u32* gAL = (const u32*)g_A2l[br] + my*128*64;
    const u32* gBH = (const u32*)g_B2h[br] + nx*128*64;
    const u32* gBL = (const u32*)g_B2l[br] + nx*128*64;
    for (int idx = tid; idx < 8192; idx += 256) {
        int row = idx >> 6, w = idx & 63, so = row*68 + w;
        AH[so] = gAH[idx]; AL[so] = gAL[idx];
        BH[so] = gBH[idx]; BL[so] = gBL[idx];
    }
    __syncthreads();

    const int wm = wid >> 2, wn = wid & 3;            // warp: M64 x N32
    const int qr = lane >> 2, qt = lane & 3;
    float acc[4][4][4] = {};
    #pragma unroll
    for (int kw = 0; kw < 64; kw += 8) {              // 8 k-steps of 16
        u32 aH[4][4], aL[4][4], bH[4][2], bL[4][2];
        #pragma unroll
        for (int mt = 0; mt < 4; mt++) {
            int base = (wm*64 + mt*16 + qr)*68 + kw + qt;
            aH[mt][0] = AH[base];         aH[mt][1] = AH[base + 8*68];
            aH[mt][2] = AH[base + 4];     aH[mt][3] = AH[base + 8*68 + 4];
            aL[mt][0] = AL[base];         aL[mt][1] = AL[base + 8*68];
            aL[mt][2] = AL[base + 4];     aL[mt][3] = AL[base + 8*68 + 4];
        }
        #pragma unroll
        for (int nt = 0; nt < 4; nt++) {
            int base = (wn*32 + nt*8 + qr)*68 + kw + qt;
            bH[nt][0] = BH[base]; bH[nt][1] = BH[base + 4];
            bL[nt][0] = BL[base]; bL[nt][1] = BL[base + 4];
        }
        #pragma unroll
        for (int mt = 0; mt < 4; mt++)
            #pragma unroll
            for (int nt = 0; nt < 4; nt++) {
                MMA16816(acc[mt][nt], aH[mt], bH[nt]);
                MMA16816(acc[mt][nt], aH[mt], bL[nt]);
                MMA16816(acc[mt][nt], aL[mt], bH[nt]);
            }
    }
    __syncthreads();
    float* Cs = (float*)smw;                           // 128 x 132
    #pragma unroll
    for (int mt = 0; mt < 4; mt++)
        #pragma unroll
        for (int nt = 0; nt < 4; nt++) {
            int r0 = wm*64 + mt*16 + qr, c0 = wn*32 + nt*8 + qt*2;
            Cs[r0*132 + c0]       = acc[mt][nt][0];
            Cs[r0*132 + c0 + 1]   = acc[mt][nt][1];
            Cs[(r0+8)*132 + c0]   = acc[mt][nt][2];
            Cs[(r0+8)*132 + c0+1] = acc[mt][nt][3];
        }
    __syncthreads();
    for (int o = tid; o < 1984; o += 256) {            // 8b x 8co x 31t
        int t = o % 31, tmp = o / 31;
        int co_l = tmp & 7, bl = tmp >> 3;
        int lo = (t > 15) ? (t - 15) : 0;
        int hi = (t < 15) ? t : 15;
        float s = 0.f;
        for (int tp = lo; tp <= hi; tp++)
            s += Cs[(bl*16 + tp)*132 + co_l*16 + (t - tp)];
        g_y2[br][((my*8 + bl)*256 + nx*8 + co_l)*31 + t] = s;
    }
}

// ---------------- kernel: BN stats conv2 ----------------
__global__ __launch_bounds__(256) void k_bnstats2(
    const float* __restrict__ hg, const float* __restrict__ hb,
    const float* __restrict__ wg, const float* __restrict__ wb)
{
    const int co = blockIdx.x, br = blockIdx.y, b = threadIdx.x;
    const float* p = g_y2[br] + (b*256 + co)*31;
    float s = 0.f, q = 0.f;
    #pragma unroll
    for (int t = 0; t < 31; t++) { float v = p[t]; s += v; q += v*v; }
    __shared__ float s1[256], s2[256];
    s1[b] = s; s2[b] = q; __syncthreads();
    for (int off = 128; off > 0; off >>= 1) {
        if (b < off) { s1[b] += s1[b+off]; s2[b] += s2[b+off]; }
        __syncthreads();
    }
    if (b == 0) {
        const float inv = 1.f/(256.f*31.f);
        float m   = s1[0]*inv;
        float var = s2[0]*inv - m*m;
        float gam = br ? wg[co] : hg[co];
        float bet = br ? wb[co] : hb[co];
        float a   = gam*rsqrtf(var + 1e-5f);
        g_ab2[br][0][co] = a;
        g_ab2[br][1][co] = bet - m*a;
    }
}

// ---------------- prep: A3 = lrelu(bn(y2)) split, [br][m=b*32+t'][ci], t'=31 -> 0 ----------
__global__ __launch_bounds__(256) void k_prepA3()
{
    int gid = blockIdx.x*256 + threadIdx.x;   // 2 x 8192 x 128
    int br = gid >> 20, m = (gid >> 7) & 8191, cp = gid & 127;
    int b = m >> 5, tp = m & 31;
    u32 hw = 0, lw = 0;
    if (tp < 31) {
        const float* y2 = g_y2[br];
        const float* aA = g_ab2[br][0];
        const float* aS = g_ab2[br][1];
        int ci = 2*cp;
        float v0 = fmaf(aA[ci],   y2[(b*256 + ci)*31 + tp],   aS[ci]);
        float v1 = fmaf(aA[ci+1], y2[(b*256 + ci+1)*31 + tp], aS[ci+1]);
        v0 = (v0 >= 0.f) ? v0 : 0.2f*v0;
        v1 = (v1 >= 0.f) ? v1 : 0.2f*v1;
        split_pair(v0, v1, hw, lw);
    }
    ((u32*)g_A3h[br])[m*128 + cp] = hw;
    ((u32*)g_A3l[br])[m*128 + cp] = lw;
}

// ---------------- kernel: conv3 via mma.sync, fold + bias + tanh ----------------
__global__ __launch_bounds__(256) void k_conv3m(
    const float* __restrict__ bh, const float* __restrict__ bw)
{
    const int br = blockIdx.z, nx = blockIdx.x, my = blockIdx.y;
    const float* __restrict__ bias = br ? bw : bh;
    u32* AH = smw;          u32* AL = smw + 8704;
    u32* BH = smw + 17408;  u32* BL = smw + 26112;
    const int tid = threadIdx.x, lane = tid & 31, wid = tid >> 5;
    const int wm = wid >> 2, wn = wid & 3;
    const int qr = lane >> 2, qt = lane & 3;
    float acc[4][4][4] = {};
    for (int kc = 0; kc < 2; kc++) {                   // K=256 in 2 chunks of 128
        if (kc) __syncthreads();
        const u32* gAH = (const u32*)g_A3h[br] + my*128*128 + kc*64;
        const u32* gAL = (const u32*)g_A3l[br] + my*128*128 + kc*64;
        const u32* gBH = (const u32*)g_B3h[br] + nx*128*128 + kc*64;
        const u32* gBL = (const u32*)g_B3l[br] + nx*128*128 + kc*64;
        for (int idx = tid; idx < 8192; idx += 256) {
            int row = idx >> 6, w = idx & 63, so = row*68 + w;
            AH[so] = gAH[row*128 + w]; AL[so] = gAL[row*128 + w];
            BH[so] = gBH[row*128 + w]; BL[so] = gBL[row*128 + w];
        }
        __syncthreads();
        #pragma unroll
        for (int kw = 0; kw < 64; kw += 8) {
            u32 aH[4][4], aL[4][4], bH[4][2], bL[4][2];
            #pragma unroll
            for (int mt = 0; mt < 4; mt++) {
                int base = (wm*64 + mt*16 + qr)*68 + kw + qt;
                aH[mt][0] = AH[base];       aH[mt][1] = AH[base + 8*68];
                aH[mt][2] = AH[base + 4];   aH[mt][3] = AH[base + 8*68 + 4];
                aL[mt][0] = AL[base];       aL[mt][1] = AL[base + 8*68];
                aL[mt][2] = AL[base + 4];   aL[mt][3] = AL[base + 8*68 + 4];
            }
            #pragma unroll
            for (int nt = 0; nt < 4; nt++) {
                int base = (wn*32 + nt*8 + qr)*68 + kw + qt;
                bH[nt][0] = BH[base]; bH[nt][1] = BH[base + 4];
                bL[nt][0] = BL[base]; bL[nt][1] = BL[base + 4];
            }
            #pragma unroll
            for (int mt = 0; mt < 4; mt++)
                #pragma unroll
                for (int nt = 0; nt < 4; nt++) {
                    MMA16816(acc[mt][nt], aH[mt], bH[nt]);
                    MMA16816(acc[mt][nt], aH[mt], bL[nt]);
                    MMA16816(acc[mt][nt], aL[mt], bH[nt]);
                }
        }
    }
    __syncthreads();
    float* Cs = (float*)smw;                           // 128 x 132
    #pragma unroll
    for (int mt = 0; mt < 4; mt++)
        #pragma unroll
        for (int nt = 0; nt < 4; nt++) {
            int r0 = wm*64 + mt*16 + qr, c0 = wn*32 + nt*8 + qt*2;
            Cs[r0*132 + c0]       = acc[mt][nt][0];
            Cs[r0*132 + c0 + 1]   = acc[mt][nt][1];
            Cs[(r0+8)*132 + c0]   = acc[mt][nt][2];
            Cs[(r0+8)*132 + c0+1] = acc[mt][nt][3];
        }
    __syncthreads();
    // rows: bl*32 + t' (4 b), cols: co_l*2 + k (64 co). y[t] = C[t][2co] + C[t-1][2co+1] + bias
    for (int i = 0; i < 32; i++) {
        int idx = tid + i*256;                          // 8192 outputs
        int t = idx & 31, co_l = (idx >> 5) & 63, bl = idx >> 11;
        int row = bl*32 + t;
        float v = Cs[row*132 + 2*co_l];
        if (t > 0) v += Cs[(row-1)*132 + 2*co_l + 1];
        v += bias[nx*64 + co_l];
        g_hw[br][((my*4 + bl)*512 + nx*64 + co_l)*32 + t] = tanhf(v);
    }
}

// ---------------- kernel: final einsum ----------------
__global__ __launch_bounds__(256) void k_final(const float* __restrict__ coef,
                                               float* __restrict__ out)
{
    const int b = blockIdx.x, tid = threadIdx.x;
    __shared__ __align__(16) float4 cs[128];
    __shared__ __align__(16) float  hs [128*32];
    __shared__ __align__(16) float  ws2[128*32];
    const int p0 = tid*4, hh = p0 >> 5, ww0 = p0 & 31;
    float acc[4][3];
    #pragma unroll
    for (int i = 0; i < 4; i++)
        #pragma unroll
        for (int c = 0; c < 3; c++) acc[i][c] = 0.f;
    for (int chk = 0; chk < 4; chk++) {
        const int r0 = chk*128;
        __syncthreads();
        if (tid < 128) {
            const int r = r0 + tid;
            const float* cp = g_craw + b*1536 + r*3;
            float a = g_abc[0][r], sh = g_abc[1][r];
            float cf = coef[r];
            float v0 = fmaf(a, cp[0], sh); v0 = (v0 >= 0.f) ? v0 : 0.2f*v0;
            float v1 = fmaf(a, cp[1], sh); v1 = (v1 >= 0.f) ? v1 : 0.2f*v1;
            float v2 = fmaf(a, cp[2], sh); v2 = (v2 >= 0.f) ? v2 : 0.2f*v2;
            cs[tid] = make_float4(v0*cf, v1*cf, v2*cf, 0.f);
        }
        for (int idx = tid; idx < 4096; idx += 256) {
            hs [idx] = g_hw[0][(b*512 + r0)*32 + idx];
            ws2[idx] = g_hw[1][(b*512 + r0)*32 + idx];
        }
        __syncthreads();
        for (int r = 0; r < 128; r++) {
            float4 c4 = cs[r];
            float  hv = hs[r*32 + hh];
            float4 wv = *reinterpret_cast<const float4*>(&ws2[r*32 + ww0]);
            float p;
            p = hv*wv.x; acc[0][0] += p*c4.x; acc[0][1] += p*c4.y; acc[0][2] += p*c4.z;
            p = hv*wv.y; acc[1][0] += p*c4.x; acc[1][1] += p*c4.y; acc[1][2] += p*c4.z;
            p = hv*wv.z; acc[2][0] += p*c4.x; acc[2][1] += p*c4.y; acc[2][2] += p*c4.z;
            p = hv*wv.w; acc[3][0] += p*c4.x; acc[3][1] += p*c4.y; acc[3][2] += p*c4.z;
        }
    }
    #pragma unroll
    for (int c = 0; c < 3; c++)
        #pragma unroll
        for (int i = 0; i < 4; i++)
            out[((b*3 + c)*32 + hh)*32 + ww0 + i] = acc[i][c];
}

// ---------------- launch ----------------
extern "C" void kernel_launch(void* const* d_in, const int* in_sizes, int n_in,
                              void* d_out, int out_size)
{
    const float* noise = (const float*)d_in[0];
    const int*   label = (const int*)  d_in[1];
    const float* lin_w = (const float*)d_in[2];
    const float* bn0_g = (const float*)d_in[4];
    const float* bn0_b = (const float*)d_in[5];
    const float* emb   = (const float*)d_in[6];
    const float* c_w1  = (const float*)d_in[7];
    const float* c_g1  = (const float*)d_in[9];
    const float* c_be1 = (const float*)d_in[10];
    const float* h_w1  = (const float*)d_in[11];
    const float* h_g1  = (const float*)d_in[13];
    const float* h_be1 = (const float*)d_in[14];
    const float* h_w2  = (const float*)d_in[15];
    const float* h_g2  = (const float*)d_in[17];
    const float* h_be2 = (const float*)d_in[18];
    const float* h_w3  = (const float*)d_in[19];
    const float* h_b3  = (const float*)d_in[20];
    const float* w_w1  = (const float*)d_in[21];
    const float* w_g1  = (const float*)d_in[23];
    const float* w_be1 = (const float*)d_in[24];
    const float* w_w2  = (const float*)d_in[25];
    const float* w_g2  = (const float*)d_in[27];
    const float* w_be2 = (const float*)d_in[28];
    const float* w_w3  = (const float*)d_in[29];
    const float* w_b3  = (const float*)d_in[30];
    const float* coef  = (const float*)d_in[31];
    float* out = (float*)d_out;

    const int SMEM = 34816*4;  // 139264 B
    cudaFuncSetAttribute(k_conv2m, cudaFuncAttributeMaxDynamicSharedMemorySize, SMEM);
    cudaFuncSetAttribute(k_conv3m, cudaFuncAttributeMaxDynamicSharedMemorySize, SMEM);

    k_latent<<<256, 256>>>(noise, label, lin_w, bn0_g, bn0_b, emb);

    k_gemm1<<<dim3(24, 4, 1), 256>>>(c_w1, c_w1, 1536, 0);
    k_gemm1<<<dim3(32, 4, 2), 256>>>(h_w1, w_w1, 2048, 1);

    k_bnstats1<<<768, 256>>>(c_g1, c_be1, h_g1, h_be1, w_g1, w_be1);

    k_prepB<<<3072, 256>>>(h_w2, w_w2, h_w3, w_w3);
    k_prepA2<<<2048, 256>>>();

    k_conv2m<<<dim3(32, 32, 2), 256, SMEM>>>();

    k_bnstats2<<<dim3(256, 2), 256>>>(h_g2, h_be2, w_g2, w_be2);
    k_prepA3<<<8192, 256>>>();

    k_conv3m<<<dim3(8, 64, 2), 256, SMEM>>>(h_b3, w_b3);

    k_final<<<256, 256>>>(coef, out);
}

// round 9
// speedup vs baseline: 2.1374x; 1.1233x over previous
#include <cuda_runtime.h>
#include <cuda_bf16.h>
#include <math.h>
#include <stdint.h>

typedef uint32_t u32;

// ---------------- scratch (device globals; no allocation) ----------------
__device__ float g_latT [256*256];
__device__ float g_craw [256*1536];
__device__ float g_x1raw[2][256*2048];
__device__ float g_y2   [2][256*256*31];
__device__ float g_abc  [2][512];
__device__ float g_abhw [2][2][128];
__device__ float g_ab2  [2][2][256];
__device__ float g_hw   [2][256*512*32];
// fragment-order bf16 operands: A [mi][ks][lane][4 words], B [ni][ks][lane][2 words]
__device__ __align__(16) u32 g_A2f [2][256*8*32*4];
__device__ __align__(16) u32 g_A2fl[2][256*8*32*4];
__device__ __align__(16) u32 g_B2f [2][512*8*32*2];
__device__ __align__(16) u32 g_B2fl[2][512*8*32*2];
__device__ __align__(16) u32 g_A3f [2][512*16*32*4];
__device__ __align__(16) u32 g_A3fl[2][512*16*32*4];
__device__ __align__(16) u32 g_B3f [2][128*16*32*2];
__device__ __align__(16) u32 g_B3fl[2][128*16*32*2];

__device__ __forceinline__ u32 packbf(float x, float y) {
    __nv_bfloat162 t;
    t.x = __float2bfloat16(x);
    t.y = __float2bfloat16(y);
    return *reinterpret_cast<u32*>(&t);
}
__device__ __forceinline__ void split_pair(float v0, float v1, u32& hw, u32& lw) {
    __nv_bfloat16 h0 = __float2bfloat16(v0), h1 = __float2bfloat16(v1);
    float r0 = v0 - __bfloat162float(h0), r1 = v1 - __bfloat162float(h1);
    __nv_bfloat162 th; th.x = h0; th.y = h1;
    hw = *reinterpret_cast<u32*>(&th);
    lw = packbf(r0, r1);
}
__device__ __forceinline__ void wreduce2(float& s, float& q) {
    #pragma unroll
    for (int o = 16; o > 0; o >>= 1) {
        s += __shfl_xor_sync(0xffffffffu, s, o);
        q += __shfl_xor_sync(0xffffffffu, q, o);
    }
}

#define MMA16816(c, a, b) \
    asm volatile("mma.sync.aligned.m16n8k16.row.col.f32.bf16.bf16.f32 " \
                 "{%0,%1,%2,%3}, {%4,%5,%6,%7}, {%8,%9}, {%0,%1,%2,%3};" \
                 : "+f"((c)[0]), "+f"((c)[1]), "+f"((c)[2]), "+f"((c)[3]) \
                 : "r"((a)[0]), "r"((a)[1]), "r"((a)[2]), "r"((a)[3]), \
                   "r"((b)[0]), "r"((b)[1]))

// ---------------- kernel 1: latent ----------------
__global__ __launch_bounds__(256) void k_latent(
    const float* __restrict__ noise, const int* __restrict__ label,
    const float* __restrict__ lin_w, const float* __restrict__ bn0_g,
    const float* __restrict__ bn0_b, const float* __restrict__ emb)
{
    const int ch = blockIdx.x, b = threadIdx.x;
    if (ch >= 128) {
        g_latT[ch*256 + b] = emb[label[b]*128 + (ch - 128)];
        return;
    }
    __shared__ float wsm[100];
    if (b < 100) wsm[b] = lin_w[ch*100 + b];
    __syncthreads();
    const float* nr = noise + b*100;
    float z = 0.f;
    #pragma unroll 4
    for (int i = 0; i < 100; i++) z += nr[i]*wsm[i];
    float s = z, q = z*z;
    wreduce2(s, q);
    __shared__ float sp[8], qp[8];
    if ((b & 31) == 0) { sp[b >> 5] = s; qp[b >> 5] = q; }
    __syncthreads();
    float ts = 0.f, tq = 0.f;
    #pragma unroll
    for (int i = 0; i < 8; i++) { ts += sp[i]; tq += qp[i]; }
    float m   = ts*(1.f/256.f);
    float var = tq*(1.f/256.f) - m*m;
    float a   = bn0_g[ch]*rsqrtf(var + 1e-5f);
    float y   = (z - m)*a + bn0_b[ch];
    g_latT[ch*256 + b] = (y >= 0.f) ? y : 0.01f*y;
}

// ---------------- kernel 2: conv1 GEMMs (raw) ----------------
__global__ __launch_bounds__(256) void k_gemm1(
    const float* __restrict__ W0, const float* __restrict__ W1, int N, int mode)
{
    const float* __restrict__ W = (mode == 0) ? W0 : (blockIdx.z ? W1 : W0);
    float* __restrict__ O = (mode == 0) ? g_craw : g_x1raw[blockIdx.z];
    const int n0 = blockIdx.x*64, b0 = blockIdx.y*64;
    const int tid = threadIdx.x, tx = tid & 15, ty = tid >> 4;
    __shared__ float Xs[16][68], Ws[16][68];
    float acc[4][4] = {};
    for (int k0 = 0; k0 < 256; k0 += 16) {
        __syncthreads();
        for (int i = tid; i < 1024; i += 256) {
            int k = i >> 6, c = i & 63;
            Xs[k][c] = g_latT[(k0+k)*256 + b0 + c];
            Ws[k][c] = W[(k0+k)*N + n0 + c];
        }
        __syncthreads();
        #pragma unroll
        for (int k = 0; k < 16; k++) {
            float4 x4 = *(const float4*)&Xs[k][ty*4];
            float4 w4 = *(const float4*)&Ws[k][tx*4];
            float xa[4] = {x4.x, x4.y, x4.z, x4.w};
            float wa[4] = {w4.x, w4.y, w4.z, w4.w};
            #pragma unroll
            for (int i = 0; i < 4; i++)
                #pragma unroll
                for (int j = 0; j < 4; j++) acc[i][j] += xa[i]*wa[j];
        }
    }
    #pragma unroll
    for (int i = 0; i < 4; i++) {
        float4 v = make_float4(acc[i][0], acc[i][1], acc[i][2], acc[i][3]);
        *(float4*)&O[(b0 + ty*4 + i)*N + n0 + tx*4] = v;
    }
}

// ---------------- kernel 3: BN stats conv1 ----------------
__global__ __launch_bounds__(256) void k_bnstats1(
    const float* __restrict__ cg, const float* __restrict__ cb,
    const float* __restrict__ hg, const float* __restrict__ hb,
    const float* __restrict__ wg, const float* __restrict__ wb)
{
    const int bid = blockIdx.x, b = threadIdx.x;
    float s = 0.f, q = 0.f; float invn; float gam, bet;
    int which, br = 0, co;
    if (bid < 512) {
        which = 0; co = bid;
        const float* p = g_craw + b*1536 + co*3;
        #pragma unroll
        for (int l = 0; l < 3; l++) { float v = p[l]; s += v; q += v*v; }
        invn = 1.f/(256.f*3.f); gam = cg[co]; bet = cb[co];
    } else {
        which = 1; int idx = bid - 512; br = idx >> 7; co = idx & 127;
        const float* p = g_x1raw[br] + b*2048 + co*16;
        #pragma unroll
        for (int l = 0; l < 16; l++) { float v = p[l]; s += v; q += v*v; }
        invn = 1.f/(256.f*16.f);
        gam = br ? wg[co] : hg[co]; bet = br ? wb[co] : hb[co];
    }
    wreduce2(s, q);
    __shared__ float sp[8], qp[8];
    if ((b & 31) == 0) { sp[b >> 5] = s; qp[b >> 5] = q; }
    __syncthreads();
    if (b == 0) {
        float ts = 0.f, tq = 0.f;
        #pragma unroll
        for (int i = 0; i < 8; i++) { ts += sp[i]; tq += qp[i]; }
        float m   = ts*invn;
        float var = tq*invn - m*m;
        float a   = gam*rsqrtf(var + 1e-5f);
        float sh  = bet - m*a;
        if (which == 0) { g_abc[0][co] = a; g_abc[1][co] = sh; }
        else            { g_abhw[br][0][co] = a; g_abhw[br][1][co] = sh; }
    }
}

// ---------------- prep: weights -> fragment-order bf16 hi/lo ----------------
__global__ __launch_bounds__(256) void k_prepB(
    const float* __restrict__ W2h, const float* __restrict__ W2w,
    const float* __restrict__ W3h, const float* __restrict__ W3w)
{
    int gid = blockIdx.x*256 + threadIdx.x;
    if (gid < 524288) {                       // W2: 2 br x 4096 n x 64 cp
        int br = gid >> 18, n = (gid >> 6) & 4095, cp = gid & 63;
        const float* W = br ? W2w : W2h;      // row-major [ci][4096]
        float v0 = W[(2*cp)*4096 + n];
        float v1 = W[(2*cp + 1)*4096 + n];
        u32 hw, lw; split_pair(v0, v1, hw, lw);
        int ni = n >> 3, ks = cp >> 3, cpl = cp & 7;
        int lane = (n & 7)*4 + (cpl & 3), w = cpl >> 2;
        int addr = ((ni*8 + ks)*32 + lane)*2 + w;
        g_B2f [br][addr] = hw;
        g_B2fl[br][addr] = lw;
    } else {                                  // W3: 2 br x 1024 n x 128 cp
        int g2 = gid - 524288;
        int br = g2 >> 17, n = (g2 >> 7) & 1023, cp = g2 & 127;
        const float* W = br ? W3w : W3h;      // [ci][1024]
        float v0 = W[(2*cp)*1024 + n];
        float v1 = W[(2*cp + 1)*1024 + n];
        u32 hw, lw; split_pair(v0, v1, hw, lw);
        int ni = n >> 3, ks = cp >> 3, cpl = cp & 7;
        int lane = (n & 7)*4 + (cpl & 3), w = cpl >> 2;
        int addr = ((ni*16 + ks)*32 + lane)*2 + w;
        g_B3f [br][addr] = hw;
        g_B3fl[br][addr] = lw;
    }
}

// ---------------- prep: A2 = lrelu(bn(x1)) -> fragment order ----------------
__global__ __launch_bounds__(256) void k_prepA2()
{
    int gid = blockIdx.x*256 + threadIdx.x;   // 2 x 4096 x 64
    int br = gid >> 18, m = (gid >> 6) & 4095, cp = gid & 63;
    int b = m >> 4, l = m & 15;
    const float* x1 = g_x1raw[br];
    const float* aA = g_abhw[br][0];
    const float* aS = g_abhw[br][1];
    int ci = 2*cp;
    float v0 = fmaf(aA[ci],   x1[b*2048 + ci*16 + l],     aS[ci]);
    float v1 = fmaf(aA[ci+1], x1[b*2048 + (ci+1)*16 + l], aS[ci+1]);
    v0 = (v0 >= 0.f) ? v0 : 0.2f*v0;
    v1 = (v1 >= 0.f) ? v1 : 0.2f*v1;
    u32 hw, lw; split_pair(v0, v1, hw, lw);
    int mi = m >> 4, r = m & 15;
    int ks = cp >> 3, cpl = cp & 7;
    int lane = (r & 7)*4 + (cpl & 3);
    int w = (cpl >> 2)*2 + (r >> 3);
    int addr = ((mi*8 + ks)*32 + lane)*4 + w;
    g_A2f [br][addr] = hw;
    g_A2fl[br][addr] = lw;
}

// ---------------- conv2: fragment-direct mma.sync ----------------
// C[(b,l)][(co,k)] = A2 @ B2^T; fold antidiagonals -> y2.
extern __shared__ u32 smw[];
__global__ __launch_bounds__(256) void k_conv2f()
{
    const int br = blockIdx.z, nx = blockIdx.x, my = blockIdx.y;
    const int tid = threadIdx.x, lane = tid & 31, wid = tid >> 5;
    const int wm = wid >> 2, wn = wid & 3;
    const u32* __restrict__ AH = g_A2f [br];
    const u32* __restrict__ AL = g_A2fl[br];
    const u32* __restrict__ BH = g_B2f [br];
    const u32* __restrict__ BL = g_B2fl[br];
    const int mi0 = my*8 + wm*4;
    const int ni0 = nx*16 + wn*4;
    float acc[4][4][4] = {};
    #pragma unroll
    for (int ks = 0; ks < 8; ks++) {
        u32 bh[4][2], bl[4][2];
        #pragma unroll
        for (int nt = 0; nt < 4; nt++) {
            int ba = (((ni0+nt)*8 + ks)*32 + lane)*2;
            uint2 vh = *(const uint2*)(BH + ba); bh[nt][0] = vh.x; bh[nt][1] = vh.y;
            uint2 vl = *(const uint2*)(BL + ba); bl[nt][0] = vl.x; bl[nt][1] = vl.y;
        }
        #pragma unroll
        for (int mt = 0; mt < 4; mt++) {
            int aa = (((mi0+mt)*8 + ks)*32 + lane)*4;
            uint4 vh = *(const uint4*)(AH + aa);
            uint4 vl = *(const uint4*)(AL + aa);
            u32 ah[4] = {vh.x, vh.y, vh.z, vh.w};
            u32 al[4] = {vl.x, vl.y, vl.z, vl.w};
            #pragma unroll
            for (int nt = 0; nt < 4; nt++) {
                MMA16816(acc[mt][nt], ah, bh[nt]);
                MMA16816(acc[mt][nt], ah, bl[nt]);
                MMA16816(acc[mt][nt], al, bh[nt]);
            }
        }
    }
    float* Cs = (float*)smw;                    // 128 x 132
    const int qr = lane >> 2, qt = lane & 3;
    #pragma unroll
    for (int mt = 0; mt < 4; mt++)
        #pragma unroll
        for (int nt = 0; nt < 4; nt++) {
            int r0 = wm*64 + mt*16 + qr, c0 = wn*32 + nt*8 + qt*2;
            Cs[r0*132 + c0]       = acc[mt][nt][0];
            Cs[r0*132 + c0 + 1]   = acc[mt][nt][1];
            Cs[(r0+8)*132 + c0]   = acc[mt][nt][2];
            Cs[(r0+8)*132 + c0+1] = acc[mt][nt][3];
        }
    __syncthreads();
    for (int o = tid; o < 1984; o += 256) {     // 8b x 8co x 31t
        int t = o % 31, tmp = o / 31;
        int co_l = tmp & 7, bl2 = tmp >> 3;
        int lo = (t > 15) ? (t - 15) : 0;
        int hi = (t < 15) ? t : 15;
        float s = 0.f;
        for (int tp = lo; tp <= hi; tp++)
            s += Cs[(bl2*16 + tp)*132 + co_l*16 + (t - tp)];
        g_y2[br][((my*8 + bl2)*256 + nx*8 + co_l)*31 + t] = s;
    }
}

// ---------------- kernel: BN stats conv2 ----------------
__global__ __launch_bounds__(256) void k_bnstats2(
    const float* __restrict__ hg, const float* __restrict__ hb,
    const float* __restrict__ wg, const float* __restrict__ wb)
{
    const int co = blockIdx.x, br = blockIdx.y, b = threadIdx.x;
    const float* p = g_y2[br] + (b*256 + co)*31;
    float s = 0.f, q = 0.f;
    #pragma unroll
    for (int t = 0; t < 31; t++) { float v = p[t]; s += v; q += v*v; }
    wreduce2(s, q);
    __shared__ float sp[8], qp[8];
    if ((b & 31) == 0) { sp[b >> 5] = s; qp[b >> 5] = q; }
    __syncthreads();
    if (b == 0) {
        float ts = 0.f, tq = 0.f;
        #pragma unroll
        for (int i = 0; i < 8; i++) { ts += sp[i]; tq += qp[i]; }
        const float inv = 1.f/(256.f*31.f);
        float m   = ts*inv;
        float var = tq*inv - m*m;
        float gam = br ? wg[co] : hg[co];
        float bet = br ? wb[co] : hb[co];
        float a   = gam*rsqrtf(var + 1e-5f);
        g_ab2[br][0][co] = a;
        g_ab2[br][1][co] = bet - m*a;
    }
}

// ---------------- prep: A3 = lrelu(bn(y2)) -> fragment order ----------------
__global__ __launch_bounds__(256) void k_prepA3()
{
    int gid = blockIdx.x*256 + threadIdx.x;   // 2 x 8192 x 128
    int br = gid >> 20, m = (gid >> 7) & 8191, cp = gid & 127;
    int b = m >> 5, tp = m & 31;
    u32 hw = 0, lw = 0;
    if (tp < 31) {
        const float* y2 = g_y2[br];
        const float* aA = g_ab2[br][0];
        const float* aS = g_ab2[br][1];
        int ci = 2*cp;
        float v0 = fmaf(aA[ci],   y2[(b*256 + ci)*31 + tp],   aS[ci]);
        float v1 = fmaf(aA[ci+1], y2[(b*256 + ci+1)*31 + tp], aS[ci+1]);
        v0 = (v0 >= 0.f) ? v0 : 0.2f*v0;
        v1 = (v1 >= 0.f) ? v1 : 0.2f*v1;
        split_pair(v0, v1, hw, lw);
    }
    int mi = m >> 4, r = m & 15;
    int ks = cp >> 3, cpl = cp & 7;
    int lane = (r & 7)*4 + (cpl & 3);
    int w = (cpl >> 2)*2 + (r >> 3);
    int addr = ((mi*16 + ks)*32 + lane)*4 + w;
    g_A3f [br][addr] = hw;
    g_A3fl[br][addr] = lw;
}

// ---------------- conv3: fragment-direct mma.sync, fold + bias + tanh ------
__global__ __launch_bounds__(256) void k_conv3f(
    const float* __restrict__ bh3, const float* __restrict__ bw3)
{
    const int br = blockIdx.z, nx = blockIdx.x, my = blockIdx.y;
    const float* __restrict__ bias = br ? bw3 : bh3;
    const int tid = threadIdx.x, lane = tid & 31, wid = tid >> 5;
    const int wm = wid >> 2, wn = wid & 3;
    const u32* __restrict__ AH = g_A3f [br];
    const u32* __restrict__ AL = g_A3fl[br];
    const u32* __restrict__ BH = g_B3f [br];
    const u32* __restrict__ BL = g_B3fl[br];
    const int mi0 = my*8 + wm*4;
    const int ni0 = nx*16 + wn*4;
    float acc[4][4][4] = {};
    #pragma unroll
    for (int ks = 0; ks < 16; ks++) {
        u32 bh[4][2], bl[4][2];
        #pragma unroll
        for (int nt = 0; nt < 4; nt++) {
            int ba = (((ni0+nt)*16 + ks)*32 + lane)*2;
            uint2 vh = *(const uint2*)(BH + ba); bh[nt][0] = vh.x; bh[nt][1] = vh.y;
            uint2 vl = *(const uint2*)(BL + ba); bl[nt][0] = vl.x; bl[nt][1] = vl.y;
        }
        #pragma unroll
        for (int mt = 0; mt < 4; mt++) {
            int aa = (((mi0+mt)*16 + ks)*32 + lane)*4;
            uint4 vh = *(const uint4*)(AH + aa);
            uint4 vl = *(const uint4*)(AL + aa);
            u32 ah[4] = {vh.x, vh.y, vh.z, vh.w};
            u32 al[4] = {vl.x, vl.y, vl.z, vl.w};
            #pragma unroll
            for (int nt = 0; nt < 4; nt++) {
                MMA16816(acc[mt][nt], ah, bh[nt]);
                MMA16816(acc[mt][nt], ah, bl[nt]);
                MMA16816(acc[mt][nt], al, bh[nt]);
            }
        }
    }
    float* Cs = (float*)smw;                    // 128 x 132
    const int qr = lane >> 2, qt = lane & 3;
    #pragma unroll
    for (int mt = 0; mt < 4; mt++)
        #pragma unroll
        for (int nt = 0; nt < 4; nt++) {
            int r0 = wm*64 + mt*16 + qr, c0 = wn*32 + nt*8 + qt*2;
            Cs[r0*132 + c0]       = acc[mt][nt][0];
            Cs[r0*132 + c0 + 1]   = acc[mt][nt][1];
            Cs[(r0+8)*132 + c0]   = acc[mt][nt][2];
            Cs[(r0+8)*132 + c0+1] = acc[mt][nt][3];
        }
    __syncthreads();
    // rows: bl*32 + t' (4 b per CTA), cols: co_l*2 + k (64 co per CTA)
    for (int i = 0; i < 32; i++) {
        int idx = tid + i*256;                  // 8192 outputs
        int t = idx & 31, co_l = (idx >> 5) & 63, bl2 = idx >> 11;
        int row = bl2*32 + t;
        float v = Cs[row*132 + 2*co_l];
        if (t > 0) v += Cs[(row-1)*132 + 2*co_l + 1];
        v += bias[nx*64 + co_l];
        g_hw[br][((my*4 + bl2)*512 + nx*64 + co_l)*32 + t] = tanhf(v);
    }
}

// ---------------- kernel: final einsum ----------------
__global__ __launch_bounds__(256) void k_final(const float* __restrict__ coef,
                                               float* __restrict__ out)
{
    const int b = blockIdx.x, tid = threadIdx.x;
    __shared__ __align__(16) float4 cs[128];
    __shared__ __align__(16) float  hs [128*32];
    __shared__ __align__(16) float  ws2[128*32];
    const int p0 = tid*4, hh = p0 >> 5, ww0 = p0 & 31;
    float acc[4][3];
    #pragma unroll
    for (int i = 0; i < 4; i++)
        #pragma unroll
        for (int c = 0; c < 3; c++) acc[i][c] = 0.f;
    for (int chk = 0; chk < 4; chk++) {
        const int r0 = chk*128;
        __syncthreads();
        if (tid < 128) {
            const int r = r0 + tid;
            const float* cp = g_craw + b*1536 + r*3;
            float a = g_abc[0][r], sh = g_abc[1][r];
            float cf = coef[r];
            float v0 = fmaf(a, cp[0], sh); v0 = (v0 >= 0.f) ? v0 : 0.2f*v0;
            float v1 = fmaf(a, cp[1], sh); v1 = (v1 >= 0.f) ? v1 : 0.2f*v1;
            float v2 = fmaf(a, cp[2], sh); v2 = (v2 >= 0.f) ? v2 : 0.2f*v2;
            cs[tid] = make_float4(v0*cf, v1*cf, v2*cf, 0.f);
        }
        for (int idx = tid; idx < 4096; idx += 256) {
            hs [idx] = g_hw[0][(b*512 + r0)*32 + idx];
            ws2[idx] = g_hw[1][(b*512 + r0)*32 + idx];
        }
        __syncthreads();
        for (int r = 0; r < 128; r++) {
            float4 c4 = cs[r];
            float  hv = hs[r*32 + hh];
            float4 wv = *reinterpret_cast<const float4*>(&ws2[r*32 + ww0]);
            float p;
            p = hv*wv.x; acc[0][0] += p*c4.x; acc[0][1] += p*c4.y; acc[0][2] += p*c4.z;
            p = hv*wv.y; acc[1][0] += p*c4.x; acc[1][1] += p*c4.y; acc[1][2] += p*c4.z;
            p = hv*wv.z; acc[2][0] += p*c4.x; acc[2][1] += p*c4.y; acc[2][2] += p*c4.z;
            p = hv*wv.w; acc[3][0] += p*c4.x; acc[3][1] += p*c4.y; acc[3][2] += p*c4.z;
        }
    }
    #pragma unroll
    for (int c = 0; c < 3; c++)
        #pragma unroll
        for (int i = 0; i < 4; i++)
            out[((b*3 + c)*32 + hh)*32 + ww0 + i] = acc[i][c];
}

// ---------------- launch ----------------
extern "C" void kernel_launch(void* const* d_in, const int* in_sizes, int n_in,
                              void* d_out, int out_size)
{
    const float* noise = (const float*)d_in[0];
    const int*   label = (const int*)  d_in[1];
    const float* lin_w = (const float*)d_in[2];
    const float* bn0_g = (const float*)d_in[4];
    const float* bn0_b = (const float*)d_in[5];
    const float* emb   = (const float*)d_in[6];
    const float* c_w1  = (const float*)d_in[7];
    const float* c_g1  = (const float*)d_in[9];
    const float* c_be1 = (const float*)d_in[10];
    const float* h_w1  = (const float*)d_in[11];
    const float* h_g1  = (const float*)d_in[13];
    const float* h_be1 = (const float*)d_in[14];
    const float* h_w2  = (const float*)d_in[15];
    const float* h_g2  = (const float*)d_in[17];
    const float* h_be2 = (const float*)d_in[18];
    const float* h_w3  = (const float*)d_in[19];
    const float* h_b3  = (const float*)d_in[20];
    const float* w_w1  = (const float*)d_in[21];
    const float* w_g1  = (const float*)d_in[23];
    const float* w_be1 = (const float*)d_in[24];
    const float* w_w2  = (const float*)d_in[25];
    const float* w_g2  = (const float*)d_in[27];
    const float* w_be2 = (const float*)d_in[28];
    const float* w_w3  = (const float*)d_in[29];
    const float* w_b3  = (const float*)d_in[30];
    const float* coef  = (const float*)d_in[31];
    float* out = (float*)d_out;

    const int SMEM = 128*132*4;  // 67584 B (epilogue C buffer)
    cudaFuncSetAttribute(k_conv2f, cudaFuncAttributeMaxDynamicSharedMemorySize, SMEM);
    cudaFuncSetAttribute(k_conv3f, cudaFuncAttributeMaxDynamicSharedMemorySize, SMEM);

    k_latent<<<256, 256>>>(noise, label, lin_w, bn0_g, bn0_b, emb);

    k_gemm1<<<dim3(24, 4, 1), 256>>>(c_w1, c_w1, 1536, 0);
    k_gemm1<<<dim3(32, 4, 2), 256>>>(h_w1, w_w1, 2048, 1);

    k_bnstats1<<<768, 256>>>(c_g1, c_be1, h_g1, h_be1, w_g1, w_be1);

    k_prepB<<<3072, 256>>>(h_w2, w_w2, h_w3, w_w3);
    k_prepA2<<<2048, 256>>>();

    k_conv2f<<<dim3(32, 32, 2), 256, SMEM>>>();

    k_bnstats2<<<dim3(256, 2), 256>>>(h_g2, h_be2, w_g2, w_be2);
    k_prepA3<<<8192, 256>>>();

    k_conv3f<<<dim3(8, 64, 2), 256, SMEM>>>(h_b3, w_b3);

    k_final<<<256, 256>>>(coef, out);
}

// round 11
// speedup vs baseline: 2.9692x; 1.3892x over previous
#include <cuda_runtime.h>
#include <cuda_bf16.h>
#include <math.h>
#include <stdint.h>

typedef uint32_t u32;

// ---------------- scratch (device globals; no allocation) ----------------
__device__ float g_latT [256*256];
__device__ float g_craw [256*1536];
__device__ float g_x1raw[2][256*2048];
__device__ float g_y2   [2][256*256*31];
__device__ float g_abc  [2][512];
__device__ float g_abhw [2][2][128];
__device__ float g_ab2  [2][2][256];
__device__ float g_hw   [2][256*512*32];
// fragment-order bf16 operands: A [mi][ks][lane][4 words], B [ni][ks][lane][2 words]
__device__ __align__(16) u32 g_A2f [2][256*8*32*4];
__device__ __align__(16) u32 g_A2fl[2][256*8*32*4];
__device__ __align__(16) u32 g_B2f [2][512*8*32*2];
__device__ __align__(16) u32 g_B2fl[2][512*8*32*2];
__device__ __align__(16) u32 g_A3f [2][512*16*32*4];
__device__ __align__(16) u32 g_A3fl[2][512*16*32*4];
__device__ __align__(16) u32 g_B3f [2][128*16*32*2];
__device__ __align__(16) u32 g_B3fl[2][128*16*32*2];

__device__ __forceinline__ u32 packbf(float x, float y) {
    __nv_bfloat162 t;
    t.x = __float2bfloat16(x);
    t.y = __float2bfloat16(y);
    return *reinterpret_cast<u32*>(&t);
}
__device__ __forceinline__ void split_pair(float v0, float v1, u32& hw, u32& lw) {
    __nv_bfloat16 h0 = __float2bfloat16(v0), h1 = __float2bfloat16(v1);
    float r0 = v0 - __bfloat162float(h0), r1 = v1 - __bfloat162float(h1);
    __nv_bfloat162 th; th.x = h0; th.y = h1;
    hw = *reinterpret_cast<u32*>(&th);
    lw = packbf(r0, r1);
}
__device__ __forceinline__ void wreduce2(float& s, float& q) {
    #pragma unroll
    for (int o = 16; o > 0; o >>= 1) {
        s += __shfl_xor_sync(0xffffffffu, s, o);
        q += __shfl_xor_sync(0xffffffffu, q, o);
    }
}

#define MMA16816(c, a, b) \
    asm volatile("mma.sync.aligned.m16n8k16.row.col.f32.bf16.bf16.f32 " \
                 "{%0,%1,%2,%3}, {%4,%5,%6,%7}, {%8,%9}, {%0,%1,%2,%3};" \
                 : "+f"((c)[0]), "+f"((c)[1]), "+f"((c)[2]), "+f"((c)[3]) \
                 : "r"((a)[0]), "r"((a)[1]), "r"((a)[2]), "r"((a)[3]), \
                   "r"((b)[0]), "r"((b)[1]))

// ---------------- kernel 1: latent + prepB combo (independent work) ----------------
__global__ __launch_bounds__(256) void k_combo(
    const float* __restrict__ noise, const int* __restrict__ label,
    const float* __restrict__ lin_w, const float* __restrict__ bn0_g,
    const float* __restrict__ bn0_b, const float* __restrict__ emb,
    const float* __restrict__ W2h, const float* __restrict__ W2w,
    const float* __restrict__ W3h, const float* __restrict__ W3w)
{
    const int bid = blockIdx.x, tid = threadIdx.x;
    if (bid < 256) {
        // ---- latent ----
        const int ch = bid, b = tid;
        if (ch >= 128) {
            g_latT[ch*256 + b] = emb[label[b]*128 + (ch - 128)];
            return;
        }
        __shared__ float wsm[100];
        if (b < 100) wsm[b] = lin_w[ch*100 + b];
        __syncthreads();
        const float* nr = noise + b*100;
        float z = 0.f;
        #pragma unroll 4
        for (int i = 0; i < 100; i++) z += nr[i]*wsm[i];
        float s = z, q = z*z;
        wreduce2(s, q);
        __shared__ float sp[8], qp[8];
        if ((b & 31) == 0) { sp[b >> 5] = s; qp[b >> 5] = q; }
        __syncthreads();
        float ts = 0.f, tq = 0.f;
        #pragma unroll
        for (int i = 0; i < 8; i++) { ts += sp[i]; tq += qp[i]; }
        float m   = ts*(1.f/256.f);
        float var = tq*(1.f/256.f) - m*m;
        float a   = bn0_g[ch]*rsqrtf(var + 1e-5f);
        float y   = (z - m)*a + bn0_b[ch];
        g_latT[ch*256 + b] = (y >= 0.f) ? y : 0.01f*y;
        return;
    }
    // ---- prepB: weights -> fragment-order bf16 hi/lo ----
    int gid = (bid - 256)*256 + tid;
    if (gid < 524288) {                       // W2: 2 br x 4096 n x 64 cp
        int br = gid >> 18, n = (gid >> 6) & 4095, cp = gid & 63;
        const float* W = br ? W2w : W2h;      // row-major [ci][4096]
        float v0 = W[(2*cp)*4096 + n];
        float v1 = W[(2*cp + 1)*4096 + n];
        u32 hw, lw; split_pair(v0, v1, hw, lw);
        int ni = n >> 3, ks = cp >> 3, cpl = cp & 7;
        int lane = (n & 7)*4 + (cpl & 3), w = cpl >> 2;
        int addr = ((ni*8 + ks)*32 + lane)*2 + w;
        g_B2f [br][addr] = hw;
        g_B2fl[br][addr] = lw;
    } else {                                  // W3: 2 br x 1024 n x 128 cp
        int g2 = gid - 524288;
        int br = g2 >> 17, n = (g2 >> 7) & 1023, cp = g2 & 127;
        const float* W = br ? W3w : W3h;      // [ci][1024]
        float v0 = W[(2*cp)*1024 + n];
        float v1 = W[(2*cp + 1)*1024 + n];
        u32 hw, lw; split_pair(v0, v1, hw, lw);
        int ni = n >> 3, ks = cp >> 3, cpl = cp & 7;
        int lane = (n & 7)*4 + (cpl & 3), w = cpl >> 2;
        int addr = ((ni*16 + ks)*32 + lane)*2 + w;
        g_B3f [br][addr] = hw;
        g_B3fl[br][addr] = lw;
    }
}

// ---------------- kernel 2: conv1 GEMMs, all branches (raw) ----------------
__global__ __launch_bounds__(256) void k_gemm1m(
    const float* __restrict__ Wc, const float* __restrict__ Wh,
    const float* __restrict__ Ww)
{
    const int z = blockIdx.z;
    int N; const float* W; float* O;
    if (z == 2) {
        if (blockIdx.x >= 24) return;
        N = 1536; W = Wc; O = g_craw;
    } else {
        N = 2048; W = z ? Ww : Wh; O = g_x1raw[z];
    }
    const int n0 = blockIdx.x*64, b0 = blockIdx.y*64;
    const int tid = threadIdx.x, tx = tid & 15, ty = tid >> 4;
    __shared__ float Xs[16][68], Ws[16][68];
    float acc[4][4] = {};
    for (int k0 = 0; k0 < 256; k0 += 16) {
        __syncthreads();
        for (int i = tid; i < 1024; i += 256) {
            int k = i >> 6, c = i & 63;
            Xs[k][c] = g_latT[(k0+k)*256 + b0 + c];
            Ws[k][c] = W[(k0+k)*N + n0 + c];
        }
        __syncthreads();
        #pragma unroll
        for (int k = 0; k < 16; k++) {
            float4 x4 = *(const float4*)&Xs[k][ty*4];
            float4 w4 = *(const float4*)&Ws[k][tx*4];
            float xa[4] = {x4.x, x4.y, x4.z, x4.w};
            float wa[4] = {w4.x, w4.y, w4.z, w4.w};
            #pragma unroll
            for (int i = 0; i < 4; i++)
                #pragma unroll
                for (int j = 0; j < 4; j++) acc[i][j] += xa[i]*wa[j];
        }
    }
    #pragma unroll
    for (int i = 0; i < 4; i++) {
        float4 v = make_float4(acc[i][0], acc[i][1], acc[i][2], acc[i][3]);
        *(float4*)&O[(b0 + ty*4 + i)*N + n0 + tx*4] = v;
    }
}

// ---------------- kernel 3: BN stats conv1 ----------------
__global__ __launch_bounds__(256) void k_bnstats1(
    const float* __restrict__ cg, const float* __restrict__ cb,
    const float* __restrict__ hg, const float* __restrict__ hb,
    const float* __restrict__ wg, const float* __restrict__ wb)
{
    const int bid = blockIdx.x, b = threadIdx.x;
    float s = 0.f, q = 0.f; float invn; float gam, bet;
    int which, br = 0, co;
    if (bid < 512) {
        which = 0; co = bid;
        const float* p = g_craw + b*1536 + co*3;
        #pragma unroll
        for (int l = 0; l < 3; l++) { float v = p[l]; s += v; q += v*v; }
        invn = 1.f/(256.f*3.f); gam = cg[co]; bet = cb[co];
    } else {
        which = 1; int idx = bid - 512; br = idx >> 7; co = idx & 127;
        const float* p = g_x1raw[br] + b*2048 + co*16;
        #pragma unroll
        for (int l = 0; l < 16; l++) { float v = p[l]; s += v; q += v*v; }
        invn = 1.f/(256.f*16.f);
        gam = br ? wg[co] : hg[co]; bet = br ? wb[co] : hb[co];
    }
    wreduce2(s, q);
    __shared__ float sp[8], qp[8];
    if ((b & 31) == 0) { sp[b >> 5] = s; qp[b >> 5] = q; }
    __syncthreads();
    if (b == 0) {
        float ts = 0.f, tq = 0.f;
        #pragma unroll
        for (int i = 0; i < 8; i++) { ts += sp[i]; tq += qp[i]; }
        float m   = ts*invn;
        float var = tq*invn - m*m;
        float a   = gam*rsqrtf(var + 1e-5f);
        float sh  = bet - m*a;
        if (which == 0) { g_abc[0][co] = a; g_abc[1][co] = sh; }
        else            { g_abhw[br][0][co] = a; g_abhw[br][1][co] = sh; }
    }
}

// ---------------- prepA2: per-batch smem tile, coalesced both ways ----------------
// block (b, br): load x1raw row (2048 floats), BN+lrelu+split -> fragment uint4s.
__global__ __launch_bounds__(256) void k_prepA2n()
{
    const int b = blockIdx.x, br = blockIdx.y, tid = threadIdx.x;
    __shared__ float xs[128*17];     // [ci*17 + l], padded
    __shared__ float aAs[128], aSs[128];
    for (int idx = tid; idx < 2048; idx += 256) {
        float v = g_x1raw[br][b*2048 + idx];
        xs[(idx >> 4)*17 + (idx & 15)] = v;
    }
    if (tid < 128) {
        aAs[tid] = g_abhw[br][0][tid];
        aSs[tid] = g_abhw[br][1][tid];
    }
    __syncthreads();
    const int ks = tid >> 5, lane = tid & 31;
    u32 oh[4], ol[4];
    #pragma unroll
    for (int w = 0; w < 4; w++) {
        int cpl2 = w >> 1, l3 = w & 1;
        int l   = (l3 << 3) | (lane >> 2);
        int cpl = (cpl2 << 2) | (lane & 3);
        int ci  = (ks*8 + cpl)*2;
        float v0 = fmaf(aAs[ci],   xs[ci*17 + l],     aSs[ci]);
        float v1 = fmaf(aAs[ci+1], xs[(ci+1)*17 + l], aSs[ci+1]);
        v0 = (v0 >= 0.f) ? v0 : 0.2f*v0;
        v1 = (v1 >= 0.f) ? v1 : 0.2f*v1;
        split_pair(v0, v1, oh[w], ol[w]);
    }
    int addr = ((b*8 + ks)*32 + lane)*4;
    *(uint4*)&g_A2f [br][addr] = make_uint4(oh[0], oh[1], oh[2], oh[3]);
    *(uint4*)&g_A2fl[br][addr] = make_uint4(ol[0], ol[1], ol[2], ol[3]);
}

// ---------------- conv2: fragment-direct mma.sync ----------------
extern __shared__ u32 smw[];
__global__ __launch_bounds__(256, 2) void k_conv2f()
{
    const int br = blockIdx.z, nx = blockIdx.x, my = blockIdx.y;
    const int tid = threadIdx.x, lane = tid & 31, wid = tid >> 5;
    const int wm = wid >> 2, wn = wid & 3;
    const u32* __restrict__ AH = g_A2f [br];
    const u32* __restrict__ AL = g_A2fl[br];
    const u32* __restrict__ BH = g_B2f [br];
    const u32* __restrict__ BL = g_B2fl[br];
    const int mi0 = my*8 + wm*4;
    const int ni0 = nx*16 + wn*4;
    float acc[4][4][4] = {};
    #pragma unroll
    for (int ks = 0; ks < 8; ks++) {
        u32 bh[4][2], bl[4][2];
        #pragma unroll
        for (int nt = 0; nt < 4; nt++) {
            int ba = (((ni0+nt)*8 + ks)*32 + lane)*2;
            uint2 vh = *(const uint2*)(BH + ba); bh[nt][0] = vh.x; bh[nt][1] = vh.y;
            uint2 vl = *(const uint2*)(BL + ba); bl[nt][0] = vl.x; bl[nt][1] = vl.y;
        }
        #pragma unroll
        for (int mt = 0; mt < 4; mt++) {
            int aa = (((mi0+mt)*8 + ks)*32 + lane)*4;
            uint4 vh = *(const uint4*)(AH + aa);
            uint4 vl = *(const uint4*)(AL + aa);
            u32 ah[4] = {vh.x, vh.y, vh.z, vh.w};
            u32 al[4] = {vl.x, vl.y, vl.z, vl.w};
            #pragma unroll
            for (int nt = 0; nt < 4; nt++) {
                MMA16816(acc[mt][nt], ah, bh[nt]);
                MMA16816(acc[mt][nt], ah, bl[nt]);
                MMA16816(acc[mt][nt], al, bh[nt]);
            }
        }
    }
    float* Cs = (float*)smw;                    // 128 x 132
    const int qr = lane >> 2, qt = lane & 3;
    #pragma unroll
    for (int mt = 0; mt < 4; mt++)
        #pragma unroll
        for (int nt = 0; nt < 4; nt++) {
            int r0 = wm*64 + mt*16 + qr, c0 = wn*32 + nt*8 + qt*2;
            Cs[r0*132 + c0]       = acc[mt][nt][0];
            Cs[r0*132 + c0 + 1]   = acc[mt][nt][1];
            Cs[(r0+8)*132 + c0]   = acc[mt][nt][2];
            Cs[(r0+8)*132 + c0+1] = acc[mt][nt][3];
        }
    __syncthreads();
    for (int o = tid; o < 1984; o += 256) {     // 8b x 8co x 31t
        int t = o % 31, tmp = o / 31;
        int co_l = tmp & 7, bl2 = tmp >> 3;
        int lo = (t > 15) ? (t - 15) : 0;
        int hi = (t < 15) ? t : 15;
        float s = 0.f;
        for (int tp = lo; tp <= hi; tp++)
            s += Cs[(bl2*16 + tp)*132 + co_l*16 + (t - tp)];
        g_y2[br][((my*8 + bl2)*256 + nx*8 + co_l)*31 + t] = s;
    }
}

// ---------------- kernel: BN stats conv2 ----------------
__global__ __launch_bounds__(256) void k_bnstats2(
    const float* __restrict__ hg, const float* __restrict__ hb,
    const float* __restrict__ wg, const float* __restrict__ wb)
{
    const int co = blockIdx.x, br = blockIdx.y, b = threadIdx.x;
    const float* p = g_y2[br] + (b*256 + co)*31;
    float s = 0.f, q = 0.f;
    #pragma unroll
    for (int t = 0; t < 31; t++) { float v = p[t]; s += v; q += v*v; }
    wreduce2(s, q);
    __shared__ float sp[8], qp[8];
    if ((b & 31) == 0) { sp[b >> 5] = s; qp[b >> 5] = q; }
    __syncthreads();
    if (b == 0) {
        float ts = 0.f, tq = 0.f;
        #pragma unroll
        for (int i = 0; i < 8; i++) { ts += sp[i]; tq += qp[i]; }
        const float inv = 1.f/(256.f*31.f);
        float m   = ts*inv;
        float var = tq*inv - m*m;
        float gam = br ? wg[co] : hg[co];
        float bet = br ? wb[co] : hb[co];
        float a   = gam*rsqrtf(var + 1e-5f);
        g_ab2[br][0][co] = a;
        g_ab2[br][1][co] = bet - m*a;
    }
}

// ---------------- prepA3: per-batch smem tile, coalesced both ways ----------------
// block (b, br): load y2 row (7936 floats), BN+lrelu+split -> fragment uint4s.
__global__ __launch_bounds__(256) void k_prepA3n()
{
    const int b = blockIdx.x, br = blockIdx.y, tid = threadIdx.x;
    __shared__ float ys[256*33];     // [ci*33 + t], padded
    __shared__ float aAs[256], aSs[256];
    for (int idx = tid; idx < 7936; idx += 256) {
        float v = g_y2[br][b*7936 + idx];
        ys[(idx / 31)*33 + (idx % 31)] = v;
    }
    if (tid < 256) {
        aAs[tid] = g_ab2[br][0][tid];
        aSs[tid] = g_ab2[br][1][tid];
    }
    __syncthreads();
    const int lane = tid & 31;
    #pragma unroll
    for (int it = 0; it < 2; it++) {
        const int ks = (tid >> 5) + 8*it;
        #pragma unroll
        for (int mih = 0; mih < 2; mih++) {
            u32 oh[4], ol[4];
            #pragma unroll
            for (int w = 0; w < 4; w++) {
                int cpl2 = w >> 1, r3 = w & 1;
                int r   = (r3 << 3) | (lane >> 2);
                int tp  = (mih << 4) | r;
                int cpl = (cpl2 << 2) | (lane & 3);
                int ci  = (ks*8 + cpl)*2;
                float v0 = 0.f, v1 = 0.f;
                if (tp < 31) {
                    v0 = fmaf(aAs[ci],   ys[ci*33 + tp],     aSs[ci]);
                    v1 = fmaf(aAs[ci+1], ys[(ci+1)*33 + tp], aSs[ci+1]);
                    v0 = (v0 >= 0.f) ? v0 : 0.2f*v0;
                    v1 = (v1 >= 0.f) ? v1 : 0.2f*v1;
                }
                split_pair(v0, v1, oh[w], ol[w]);
            }
            int mi = b*2 + mih;
            int addr = ((mi*16 + ks)*32 + lane)*4;
            *(uint4*)&g_A3f [br][addr] = make_uint4(oh[0], oh[1], oh[2], oh[3]);
            *(uint4*)&g_A3fl[br][addr] = make_uint4(ol[0], ol[1], ol[2], ol[3]);
        }
    }
}

// ---------------- conv3: fragment-direct mma.sync, fold + bias + tanh ------
__global__ __launch_bounds__(256, 2) void k_conv3f(
    const float* __restrict__ bh3, const float* __restrict__ bw3)
{
    const int br = blockIdx.z, nx = blockIdx.x, my = blockIdx.y;
    const float* __restrict__ bias = br ? bw3 : bh3;
    const int tid = threadIdx.x, lane = tid & 31, wid = tid >> 5;
    const int wm = wid >> 2, wn = wid & 3;
    const u32* __restrict__ AH = g_A3f [br];
    const u32* __restrict__ AL = g_A3fl[br];
    const u32* __restrict__ BH = g_B3f [br];
    const u32* __restrict__ BL = g_B3fl[br];
    const int mi0 = my*8 + wm*4;
    const int ni0 = nx*16 + wn*4;
    float acc[4][4][4] = {};
    #pragma unroll
    for (int ks = 0; ks < 16; ks++) {
        u32 bh[4][2], bl[4][2];
        #pragma unroll
        for (int nt = 0; nt < 4; nt++) {
            int ba = (((ni0+nt)*16 + ks)*32 + lane)*2;
            uint2 vh = *(const uint2*)(BH + ba); bh[nt][0] = vh.x; bh[nt][1] = vh.y;
            uint2 vl = *(const uint2*)(BL + ba); bl[nt][0] = vl.x; bl[nt][1] = vl.y;
        }
        #pragma unroll
        for (int mt = 0; mt < 4; mt++) {
            int aa = (((mi0+mt)*16 + ks)*32 + lane)*4;
            uint4 vh = *(const uint4*)(AH + aa);
            uint4 vl = *(const uint4*)(AL + aa);
            u32 ah[4] = {vh.x, vh.y, vh.z, vh.w};
            u32 al[4] = {vl.x, vl.y, vl.z, vl.w};
            #pragma unroll
            for (int nt = 0; nt < 4; nt++) {
                MMA16816(acc[mt][nt], ah, bh[nt]);
                MMA16816(acc[mt][nt], ah, bl[nt]);
                MMA16816(acc[mt][nt], al, bh[nt]);
            }
        }
    }
    float* Cs = (float*)smw;                    // 128 x 132
    const int qr = lane >> 2, qt = lane & 3;
    #pragma unroll
    for (int mt = 0; mt < 4; mt++)
        #pragma unroll
        for (int nt = 0; nt < 4; nt++) {
            int r0 = wm*64 + mt*16 + qr, c0 = wn*32 + nt*8 + qt*2;
            Cs[r0*132 + c0]       = acc[mt][nt][0];
            Cs[r0*132 + c0 + 1]   = acc[mt][nt][1];
            Cs[(r0+8)*132 + c0]   = acc[mt][nt][2];
            Cs[(r0+8)*132 + c0+1] = acc[mt][nt][3];
        }
    __syncthreads();
    // rows: bl*32 + t' (4 b per CTA), cols: co_l*2 + k (64 co per CTA)
    for (int i = 0; i < 32; i++) {
        int idx = tid + i*256;                  // 8192 outputs
        int t = idx & 31, co_l = (idx >> 5) & 63, bl2 = idx >> 11;
        int row = bl2*32 + t;
        float v = Cs[row*132 + 2*co_l];
        if (t > 0) v += Cs[(row-1)*132 + 2*co_l + 1];
        v += bias[nx*64 + co_l];
        g_hw[br][((my*4 + bl2)*512 + nx*64 + co_l)*32 + t] = tanhf(v);
    }
}

// ---------------- kernel: final einsum ----------------
__global__ __launch_bounds__(256) void k_final(const float* __restrict__ coef,
                                               float* __restrict__ out)
{
    const int b = blockIdx.x, tid = threadIdx.x;
    __shared__ __align__(16) float4 cs[128];
    __shared__ __align__(16) float  hs [128*32];
    __shared__ __align__(16) float  ws2[128*32];
    const int p0 = tid*4, hh = p0 >> 5, ww0 = p0 & 31;
    float acc[4][3];
    #pragma unroll
    for (int i = 0; i < 4; i++)
        #pragma unroll
        for (int c = 0; c < 3; c++) acc[i][c] = 0.f;
    for (int chk = 0; chk < 4; chk++) {
        const int r0 = chk*128;
        __syncthreads();
        if (tid < 128) {
            const int r = r0 + tid;
            const float* cp = g_craw + b*1536 + r*3;
            float a = g_abc[0][r], sh = g_abc[1][r];
            float cf = coef[r];
            float v0 = fmaf(a, cp[0], sh); v0 = (v0 >= 0.f) ? v0 : 0.2f*v0;
            float v1 = fmaf(a, cp[1], sh); v1 = (v1 >= 0.f) ? v1 : 0.2f*v1;
            float v2 = fmaf(a, cp[2], sh); v2 = (v2 >= 0.f) ? v2 : 0.2f*v2;
            cs[tid] = make_float4(v0*cf, v1*cf, v2*cf, 0.f);
        }
        for (int idx = tid; idx < 4096; idx += 256) {
            hs [idx] = g_hw[0][(b*512 + r0)*32 + idx];
            ws2[idx] = g_hw[1][(b*512 + r0)*32 + idx];
        }
        __syncthreads();
        for (int r = 0; r < 128; r++) {
            float4 c4 = cs[r];
            float  hv = hs[r*32 + hh];
            float4 wv = *reinterpret_cast<const float4*>(&ws2[r*32 + ww0]);
            float p;
            p = hv*wv.x; acc[0][0] += p*c4.x; acc[0][1] += p*c4.y; acc[0][2] += p*c4.z;
            p = hv*wv.y; acc[1][0] += p*c4.x; acc[1][1] += p*c4.y; acc[1][2] += p*c4.z;
            p = hv*wv.z; acc[2][0] += p*c4.x; acc[2][1] += p*c4.y; acc[2][2] += p*c4.z;
            p = hv*wv.w; acc[3][0] += p*c4.x; acc[3][1] += p*c4.y; acc[3][2] += p*c4.z;
        }
    }
    #pragma unroll
    for (int c = 0; c < 3; c++)
        #pragma unroll
        for (int i = 0; i < 4; i++)
            out[((b*3 + c)*32 + hh)*32 + ww0 + i] = acc[i][c];
}

// ---------------- launch ----------------
extern "C" void kernel_launch(void* const* d_in, const int* in_sizes, int n_in,
                              void* d_out, int out_size)
{
    const float* noise = (const float*)d_in[0];
    const int*   label = (const int*)  d_in[1];
    const float* lin_w = (const float*)d_in[2];
    const float* bn0_g = (const float*)d_in[4];
    const float* bn0_b = (const float*)d_in[5];
    const float* emb   = (const float*)d_in[6];
    const float* c_w1  = (const float*)d_in[7];
    const float* c_g1  = (const float*)d_in[9];
    const float* c_be1 = (const float*)d_in[10];
    const float* h_w1  = (const float*)d_in[11];
    const float* h_g1  = (const float*)d_in[13];
    const float* h_be1 = (const float*)d_in[14];
    const float* h_w2  = (const float*)d_in[15];
    const float* h_g2  = (const float*)d_in[17];
    const float* h_be2 = (const float*)d_in[18];
    const float* h_w3  = (const float*)d_in[19];
    const float* h_b3  = (const float*)d_in[20];
    const float* w_w1  = (const float*)d_in[21];
    const float* w_g1  = (const float*)d_in[23];
    const float* w_be1 = (const float*)d_in[24];
    const float* w_w2  = (const float*)d_in[25];
    const float* w_g2  = (const float*)d_in[27];
    const float* w_be2 = (const float*)d_in[28];
    const float* w_w3  = (const float*)d_in[29];
    const float* w_b3  = (const float*)d_in[30];
    const float* coef  = (const float*)d_in[31];
    float* out = (float*)d_out;

    const int SMEM = 128*132*4;  // 67584 B (epilogue C buffer)
    cudaFuncSetAttribute(k_conv2f, cudaFuncAttributeMaxDynamicSharedMemorySize, SMEM);
    cudaFuncSetAttribute(k_conv3f, cudaFuncAttributeMaxDynamicSharedMemorySize, SMEM);

    k_combo<<<3328, 256>>>(noise, label, lin_w, bn0_g, bn0_b, emb,
                           h_w2, w_w2, h_w3, w_w3);

    k_gemm1m<<<dim3(32, 4, 3), 256>>>(c_w1, h_w1, w_w1);

    k_bnstats1<<<768, 256>>>(c_g1, c_be1, h_g1, h_be1, w_g1, w_be1);

    k_prepA2n<<<dim3(256, 2), 256>>>();

    k_conv2f<<<dim3(32, 32, 2), 256, SMEM>>>();

    k_bnstats2<<<dim3(256, 2), 256>>>(h_g2, h_be2, w_g2, w_be2);

    k_prepA3n<<<dim3(256, 2), 256>>>();

    k_conv3f<<<dim3(8, 64, 2), 256, SMEM>>>(h_b3, w_b3);

    k_final<<<256, 256>>>(coef, out);
}